// round 1
// baseline (speedup 1.0000x reference)
#include <cuda_runtime.h>
#include <math.h>

#define D_MODEL 1024
#define D_FFN   2048
#define N_TOK   4096
#define N_EXP   8
#define MAXSLOT 9216              /* 2*N_TOK + 8*128 padding */
#define NT_GU   (MAXSLOT / 64)    /* 144 gate/up row tiles   */
#define NT_DN   (MAXSLOT / 128)   /* 72 down row tiles       */

// ---------------- scratch (static device globals; no runtime allocation) ----
__device__ float g_Hshared[(size_t)N_TOK * D_FFN];     // 32 MB
__device__ float g_Hexp[(size_t)MAXSLOT * D_FFN];      // 75.5 MB
__device__ int   g_slot_token[MAXSLOT];
__device__ float g_slot_w[MAXSLOT];
__device__ int   g_counts[N_EXP];
__device__ float g_psum[N_EXP];
__device__ int   g_fill[N_EXP];
__device__ int   g_padoff[N_EXP + 1];
__device__ int   g_tile_gu[NT_GU];
__device__ int   g_tile_dn[NT_DN];
__device__ int   g_tok_idx[N_TOK * 2];
__device__ float g_tok_w[N_TOK * 2];

// ---------------- K1: init --------------------------------------------------
__global__ void init_kernel() {
    int i = blockIdx.x * blockDim.x + threadIdx.x;
    if (i < MAXSLOT) g_slot_token[i] = -1;
    if (i < N_EXP) { g_counts[i] = 0; g_psum[i] = 0.f; g_fill[i] = 0; }
}

// ---------------- K2: router (one warp per token) ---------------------------
__global__ void router_kernel(const float* __restrict__ x,
                              const float* __restrict__ rw) {
    int t = blockIdx.x * 4 + (threadIdx.x >> 5);
    int lane = threadIdx.x & 31;
    if (t >= N_TOK) return;
    const float* xr = x + (size_t)t * D_MODEL;
    float acc[N_EXP];
#pragma unroll
    for (int e = 0; e < N_EXP; e++) acc[e] = 0.f;
    for (int k = lane; k < D_MODEL; k += 32) {
        float xv = xr[k];
#pragma unroll
        for (int e = 0; e < N_EXP; e++) acc[e] += xv * rw[k * N_EXP + e];
    }
#pragma unroll
    for (int e = 0; e < N_EXP; e++)
#pragma unroll
        for (int o = 16; o; o >>= 1) acc[e] += __shfl_xor_sync(0xffffffffu, acc[e], o);

    if (lane == 0) {
        // stable top-2 (matches jax.lax.top_k tie-breaking: first index wins)
        int i0 = 0; float v0 = acc[0];
#pragma unroll
        for (int e = 1; e < N_EXP; e++) if (acc[e] > v0) { v0 = acc[e]; i0 = e; }
        int i1 = -1; float v1 = -1e30f;
#pragma unroll
        for (int e = 0; e < N_EXP; e++) {
            if (e == i0) continue;
            if (acc[e] > v1) { v1 = acc[e]; i1 = e; }
        }
        float m2 = fmaxf(v0, v1);
        float e0 = expf(v0 - m2), e1 = expf(v1 - m2);
        float inv = 1.f / (e0 + e1);
        g_tok_idx[t * 2 + 0] = i0;  g_tok_w[t * 2 + 0] = e0 * inv;
        g_tok_idx[t * 2 + 1] = i1;  g_tok_w[t * 2 + 1] = e1 * inv;
        atomicAdd(&g_counts[i0], 1);
        atomicAdd(&g_counts[i1], 1);
        // full softmax for aux loss
        float mm = acc[0];
#pragma unroll
        for (int e = 1; e < N_EXP; e++) mm = fmaxf(mm, acc[e]);
        float s = 0.f, ex[N_EXP];
#pragma unroll
        for (int e = 0; e < N_EXP; e++) { ex[e] = expf(acc[e] - mm); s += ex[e]; }
        float invs = 1.f / s;
#pragma unroll
        for (int e = 0; e < N_EXP; e++) atomicAdd(&g_psum[e], ex[e] * invs);
    }
}

// ---------------- K3: offsets + tile maps + aux loss ------------------------
__global__ void offsets_kernel(float* __restrict__ out, int out_size) {
    __shared__ int spad[N_EXP + 1];
    int tid = threadIdx.x;
    if (tid == 0) {
        int off = 0;
        for (int e = 0; e < N_EXP; e++) {
            g_padoff[e] = off;
            off += ((g_counts[e] + 127) / 128) * 128;
        }
        g_padoff[N_EXP] = off;
        for (int e = 0; e <= N_EXP; e++) spad[e] = g_padoff[e];
        double s = 0.0;
        for (int e = 0; e < N_EXP; e++) s += (double)g_counts[e] * (double)g_psum[e];
        float aux = (float)((double)N_EXP * s / ((double)N_TOK * (double)N_TOK));
        if (out_size > N_TOK * D_MODEL) out[(size_t)N_TOK * D_MODEL] = aux;
    }
    __syncthreads();
    for (int j = tid; j < NT_GU; j += blockDim.x) {
        int row = j * 64, te = -1;
#pragma unroll
        for (int e = 0; e < N_EXP; e++)
            if (row >= spad[e] && row < spad[e + 1]) te = e;
        g_tile_gu[j] = te;
    }
    for (int j = tid; j < NT_DN; j += blockDim.x) {
        int row = j * 128, te = -1;
#pragma unroll
        for (int e = 0; e < N_EXP; e++)
            if (row >= spad[e] && row < spad[e + 1]) te = e;
        g_tile_dn[j] = te;
    }
}

// ---------------- K4: scatter tokens into expert slots ----------------------
__global__ void scatter_kernel() {
    int t = blockIdx.x * blockDim.x + threadIdx.x;
    if (t >= N_TOK) return;
#pragma unroll
    for (int k = 0; k < 2; k++) {
        int e = g_tok_idx[t * 2 + k];
        float w = g_tok_w[t * 2 + k];
        int pos = atomicAdd(&g_fill[e], 1);
        int slot = g_padoff[e] + pos;
        g_slot_token[slot] = t;
        g_slot_w[slot] = w;
    }
}

// ---------------- K5/K7: fused gate+up GEMM + SwiGLU ------------------------
// C tile: 64(M) x 128(N), K-step 16, 256 threads, 4x8 micro-tile per output.
template <bool GATHER>
__global__ void __launch_bounds__(256) gateup_kernel(
    const float* __restrict__ X, const float* __restrict__ Wg_base,
    const float* __restrict__ Wu_base, float* __restrict__ H) {
    int by = blockIdx.y, bx = blockIdx.x;
    int te = 0;
    if (GATHER) { te = g_tile_gu[by]; if (te < 0) return; }
    const float* Wg = Wg_base + (size_t)te * D_MODEL * D_FFN;
    const float* Wu = Wu_base + (size_t)te * D_MODEL * D_FFN;
    int n0 = bx * 128;
    int r0 = by * 64;

    __shared__ float As[16][64];
    __shared__ float Bg[16][128];
    __shared__ float Bu[16][128];

    int tid = threadIdx.x;
    int arow = tid >> 2, akq = tid & 3;          // A loader: 1 float4 / thread
    int tm = tid >> 4, tn = tid & 15;            // 16x16 thread grid

    int tok;
    if (GATHER) tok = g_slot_token[r0 + arow];
    else        tok = r0 + arow;
    const float4* axp = (tok >= 0) ? (const float4*)(X + (size_t)tok * D_MODEL)
                                   : (const float4*)0;

    float accg[4][8], accu[4][8];
#pragma unroll
    for (int i = 0; i < 4; i++)
#pragma unroll
        for (int j = 0; j < 8; j++) { accg[i][j] = 0.f; accu[i][j] = 0.f; }

    for (int kt = 0; kt < D_MODEL; kt += 16) {
        float4 av = axp ? axp[(kt >> 2) + akq] : make_float4(0.f, 0.f, 0.f, 0.f);
        As[akq * 4 + 0][arow] = av.x;
        As[akq * 4 + 1][arow] = av.y;
        As[akq * 4 + 2][arow] = av.z;
        As[akq * 4 + 3][arow] = av.w;
#pragma unroll
        for (int l = 0; l < 2; l++) {
            int idx = tid + l * 256;
            int brow = idx >> 5, c4 = idx & 31;
            const float* gsrc = Wg + (size_t)(kt + brow) * D_FFN + n0 + c4 * 4;
            const float* usrc = Wu + (size_t)(kt + brow) * D_FFN + n0 + c4 * 4;
            *(float4*)&Bg[brow][c4 * 4] = *(const float4*)gsrc;
            *(float4*)&Bu[brow][c4 * 4] = *(const float4*)usrc;
        }
        __syncthreads();
#pragma unroll
        for (int k = 0; k < 16; k++) {
            float4 a4 = *(const float4*)&As[k][tm * 4];
            float4 g0 = *(const float4*)&Bg[k][tn * 8];
            float4 g1 = *(const float4*)&Bg[k][tn * 8 + 4];
            float4 u0 = *(const float4*)&Bu[k][tn * 8];
            float4 u1 = *(const float4*)&Bu[k][tn * 8 + 4];
            float aa[4] = {a4.x, a4.y, a4.z, a4.w};
            float gg[8] = {g0.x, g0.y, g0.z, g0.w, g1.x, g1.y, g1.z, g1.w};
            float uu[8] = {u0.x, u0.y, u0.z, u0.w, u1.x, u1.y, u1.z, u1.w};
#pragma unroll
            for (int i = 0; i < 4; i++)
#pragma unroll
                for (int j = 0; j < 8; j++) {
                    accg[i][j] += aa[i] * gg[j];
                    accu[i][j] += aa[i] * uu[j];
                }
        }
        __syncthreads();
    }
#pragma unroll
    for (int i = 0; i < 4; i++) {
        int r = r0 + tm * 4 + i;
        float* hp = H + (size_t)r * D_FFN + n0 + tn * 8;
#pragma unroll
        for (int j = 0; j < 8; j++) {
            float g = accg[i][j];
            float h = g * (1.f / (1.f + __expf(-g))) * accu[i][j];
            hp[j] = h;
        }
    }
}

// ---------------- K6/K8: down GEMM -------------------------------------------
// C tile: 128 x 128, K-step 16, 256 threads, 8x8 micro-tile per thread.
template <bool EXPERT>
__global__ void __launch_bounds__(256) down_kernel(
    const float* __restrict__ Hbuf, const float* __restrict__ Wd_base,
    float* __restrict__ out) {
    int by = blockIdx.y, bx = blockIdx.x;
    int te = 0;
    if (EXPERT) { te = g_tile_dn[by]; if (te < 0) return; }
    const float* Wd = Wd_base + (size_t)te * D_FFN * D_MODEL;
    int n0 = bx * 128, r0 = by * 128;

    __shared__ float As[16][128];
    __shared__ float Bs[16][128];

    int tid = threadIdx.x;
    int tm = tid >> 4, tn = tid & 15;
    float acc[8][8];
#pragma unroll
    for (int i = 0; i < 8; i++)
#pragma unroll
        for (int j = 0; j < 8; j++) acc[i][j] = 0.f;

    for (int kt = 0; kt < D_FFN; kt += 16) {
#pragma unroll
        for (int l = 0; l < 2; l++) {
            int idx = tid + l * 256;
            int arow = idx >> 2, akq = idx & 3;
            float4 av = *(const float4*)(Hbuf + (size_t)(r0 + arow) * D_FFN + kt + akq * 4);
            As[akq * 4 + 0][arow] = av.x;
            As[akq * 4 + 1][arow] = av.y;
            As[akq * 4 + 2][arow] = av.z;
            As[akq * 4 + 3][arow] = av.w;
            int brow = idx >> 5, c4 = idx & 31;
            *(float4*)&Bs[brow][c4 * 4] =
                *(const float4*)(Wd + (size_t)(kt + brow) * D_MODEL + n0 + c4 * 4);
        }
        __syncthreads();
#pragma unroll
        for (int k = 0; k < 16; k++) {
            float4 a0 = *(const float4*)&As[k][tm * 8];
            float4 a1 = *(const float4*)&As[k][tm * 8 + 4];
            float4 b0 = *(const float4*)&Bs[k][tn * 8];
            float4 b1 = *(const float4*)&Bs[k][tn * 8 + 4];
            float aa[8] = {a0.x, a0.y, a0.z, a0.w, a1.x, a1.y, a1.z, a1.w};
            float bb[8] = {b0.x, b0.y, b0.z, b0.w, b1.x, b1.y, b1.z, b1.w};
#pragma unroll
            for (int i = 0; i < 8; i++)
#pragma unroll
                for (int j = 0; j < 8; j++) acc[i][j] += aa[i] * bb[j];
        }
        __syncthreads();
    }

    if (EXPERT) {
#pragma unroll
        for (int i = 0; i < 8; i++) {
            int r = r0 + tm * 8 + i;
            int tok = g_slot_token[r];
            if (tok < 0) continue;
            float w = g_slot_w[r];
            float* op = out + (size_t)tok * D_MODEL + n0 + tn * 8;
#pragma unroll
            for (int j = 0; j < 8; j++) atomicAdd(&op[j], w * acc[i][j]);
        }
    } else {
#pragma unroll
        for (int i = 0; i < 8; i++) {
            int r = r0 + tm * 8 + i;
            float* op = out + (size_t)r * D_MODEL + n0 + tn * 8;
#pragma unroll
            for (int j = 0; j < 8; j++) op[j] = acc[i][j];
        }
    }
}

// ---------------- launch ------------------------------------------------------
extern "C" void kernel_launch(void* const* d_in, const int* in_sizes, int n_in,
                              void* d_out, int out_size) {
    const float* x         = (const float*)d_in[0];
    const float* shared_wg = (const float*)d_in[1];
    const float* shared_wu = (const float*)d_in[2];
    const float* shared_wd = (const float*)d_in[3];
    const float* exp_wg    = (const float*)d_in[4];
    const float* exp_wu    = (const float*)d_in[5];
    const float* exp_wd    = (const float*)d_in[6];
    const float* router_w  = (const float*)d_in[7];
    float* out = (float*)d_out;

    float* Hshared; cudaGetSymbolAddress((void**)&Hshared, g_Hshared);
    float* Hexp;    cudaGetSymbolAddress((void**)&Hexp, g_Hexp);

    init_kernel<<<(MAXSLOT + 255) / 256, 256>>>();
    router_kernel<<<N_TOK / 4, 128>>>(x, router_w);
    offsets_kernel<<<1, 128>>>(out, out_size);
    scatter_kernel<<<N_TOK / 256, 256>>>();

    // shared expert
    gateup_kernel<false><<<dim3(D_FFN / 128, N_TOK / 64), 256>>>(
        x, shared_wg, shared_wu, Hshared);
    down_kernel<false><<<dim3(D_MODEL / 128, N_TOK / 128), 256>>>(
        Hshared, shared_wd, out);

    // routed experts (gathered)
    gateup_kernel<true><<<dim3(D_FFN / 128, NT_GU), 256>>>(
        x, exp_wg, exp_wu, Hexp);
    down_kernel<true><<<dim3(D_MODEL / 128, NT_DN), 256>>>(
        Hexp, exp_wd, out);
}

// round 2
// speedup vs baseline: 1.0023x; 1.0023x over previous
#include <cuda_runtime.h>
#include <math.h>

#define D_MODEL 1024
#define D_FFN   2048
#define N_TOK   4096
#define N_EXP   8
#define MAXSLOT 9216              /* 2*N_TOK + 8*128 padding */
#define NT_GU   (MAXSLOT / 64)    /* 144 gate/up row tiles   */
#define NT_DN   (MAXSLOT / 128)   /* 72 down row tiles       */

// ---------------- scratch (static device globals; no runtime allocation) ----
__device__ float g_Hshared[(size_t)N_TOK * D_FFN];     // 32 MB
__device__ float g_Hexp[(size_t)MAXSLOT * D_FFN];      // 75.5 MB
__device__ int   g_slot_token[MAXSLOT];
__device__ float g_slot_w[MAXSLOT];
__device__ int   g_counts[N_EXP];
__device__ float g_psum[N_EXP];
__device__ int   g_fill[N_EXP];
__device__ int   g_padoff[N_EXP + 1];
__device__ int   g_tile_gu[NT_GU];
__device__ int   g_tile_dn[NT_DN];
__device__ int   g_tok_idx[N_TOK * 2];
__device__ float g_tok_w[N_TOK * 2];

// ---------------- K1: init --------------------------------------------------
__global__ void init_kernel() {
    int i = blockIdx.x * blockDim.x + threadIdx.x;
    if (i < MAXSLOT) g_slot_token[i] = -1;
    if (i < N_EXP) { g_counts[i] = 0; g_psum[i] = 0.f; g_fill[i] = 0; }
}

// ---------------- K2: router (one warp per token) ---------------------------
__global__ void router_kernel(const float* __restrict__ x,
                              const float* __restrict__ rw) {
    int t = blockIdx.x * 4 + (threadIdx.x >> 5);
    int lane = threadIdx.x & 31;
    if (t >= N_TOK) return;
    const float* xr = x + (size_t)t * D_MODEL;
    float acc[N_EXP];
#pragma unroll
    for (int e = 0; e < N_EXP; e++) acc[e] = 0.f;
    for (int k = lane; k < D_MODEL; k += 32) {
        float xv = xr[k];
#pragma unroll
        for (int e = 0; e < N_EXP; e++) acc[e] += xv * rw[k * N_EXP + e];
    }
#pragma unroll
    for (int e = 0; e < N_EXP; e++)
#pragma unroll
        for (int o = 16; o; o >>= 1) acc[e] += __shfl_xor_sync(0xffffffffu, acc[e], o);

    if (lane == 0) {
        // stable top-2 (matches jax.lax.top_k tie-breaking: first index wins)
        int i0 = 0; float v0 = acc[0];
#pragma unroll
        for (int e = 1; e < N_EXP; e++) if (acc[e] > v0) { v0 = acc[e]; i0 = e; }
        int i1 = -1; float v1 = -1e30f;
#pragma unroll
        for (int e = 0; e < N_EXP; e++) {
            if (e == i0) continue;
            if (acc[e] > v1) { v1 = acc[e]; i1 = e; }
        }
        float m2 = fmaxf(v0, v1);
        float e0 = expf(v0 - m2), e1 = expf(v1 - m2);
        float inv = 1.f / (e0 + e1);
        g_tok_idx[t * 2 + 0] = i0;  g_tok_w[t * 2 + 0] = e0 * inv;
        g_tok_idx[t * 2 + 1] = i1;  g_tok_w[t * 2 + 1] = e1 * inv;
        atomicAdd(&g_counts[i0], 1);
        atomicAdd(&g_counts[i1], 1);
        // full softmax for aux loss
        float mm = acc[0];
#pragma unroll
        for (int e = 1; e < N_EXP; e++) mm = fmaxf(mm, acc[e]);
        float s = 0.f, ex[N_EXP];
#pragma unroll
        for (int e = 0; e < N_EXP; e++) { ex[e] = expf(acc[e] - mm); s += ex[e]; }
        float invs = 1.f / s;
#pragma unroll
        for (int e = 0; e < N_EXP; e++) atomicAdd(&g_psum[e], ex[e] * invs);
    }
}

// ---------------- K3: offsets + tile maps + aux loss ------------------------
__global__ void offsets_kernel(float* __restrict__ out, int out_size) {
    __shared__ int spad[N_EXP + 1];
    int tid = threadIdx.x;
    if (tid == 0) {
        int off = 0;
        for (int e = 0; e < N_EXP; e++) {
            g_padoff[e] = off;
            off += ((g_counts[e] + 127) / 128) * 128;
        }
        g_padoff[N_EXP] = off;
        for (int e = 0; e <= N_EXP; e++) spad[e] = g_padoff[e];
        double s = 0.0;
        for (int e = 0; e < N_EXP; e++) s += (double)g_counts[e] * (double)g_psum[e];
        float aux = (float)((double)N_EXP * s / ((double)N_TOK * (double)N_TOK));
        if (out_size > N_TOK * D_MODEL) out[(size_t)N_TOK * D_MODEL] = aux;
    }
    __syncthreads();
    for (int j = tid; j < NT_GU; j += blockDim.x) {
        int row = j * 64, te = -1;
#pragma unroll
        for (int e = 0; e < N_EXP; e++)
            if (row >= spad[e] && row < spad[e + 1]) te = e;
        g_tile_gu[j] = te;
    }
    for (int j = tid; j < NT_DN; j += blockDim.x) {
        int row = j * 128, te = -1;
#pragma unroll
        for (int e = 0; e < N_EXP; e++)
            if (row >= spad[e] && row < spad[e + 1]) te = e;
        g_tile_dn[j] = te;
    }
}

// ---------------- K4: scatter tokens into expert slots ----------------------
__global__ void scatter_kernel() {
    int t = blockIdx.x * blockDim.x + threadIdx.x;
    if (t >= N_TOK) return;
#pragma unroll
    for (int k = 0; k < 2; k++) {
        int e = g_tok_idx[t * 2 + k];
        float w = g_tok_w[t * 2 + k];
        int pos = atomicAdd(&g_fill[e], 1);
        int slot = g_padoff[e] + pos;
        g_slot_token[slot] = t;
        g_slot_w[slot] = w;
    }
}

// ---------------- K5/K7: fused gate+up GEMM + SwiGLU ------------------------
// C tile: 64(M) x 128(N), K-step 16, 256 threads, 4x8 micro-tile per output.
template <bool GATHER>
__global__ void __launch_bounds__(256) gateup_kernel(
    const float* __restrict__ X, const float* __restrict__ Wg_base,
    const float* __restrict__ Wu_base, float* __restrict__ H) {
    int by = blockIdx.y, bx = blockIdx.x;
    int te = 0;
    if (GATHER) { te = g_tile_gu[by]; if (te < 0) return; }
    const float* Wg = Wg_base + (size_t)te * D_MODEL * D_FFN;
    const float* Wu = Wu_base + (size_t)te * D_MODEL * D_FFN;
    int n0 = bx * 128;
    int r0 = by * 64;

    __shared__ float As[16][64];
    __shared__ float Bg[16][128];
    __shared__ float Bu[16][128];

    int tid = threadIdx.x;
    int arow = tid >> 2, akq = tid & 3;          // A loader: 1 float4 / thread
    int tm = tid >> 4, tn = tid & 15;            // 16x16 thread grid

    int tok;
    if (GATHER) tok = g_slot_token[r0 + arow];
    else        tok = r0 + arow;
    const float4* axp = (tok >= 0) ? (const float4*)(X + (size_t)tok * D_MODEL)
                                   : (const float4*)0;

    float accg[4][8], accu[4][8];
#pragma unroll
    for (int i = 0; i < 4; i++)
#pragma unroll
        for (int j = 0; j < 8; j++) { accg[i][j] = 0.f; accu[i][j] = 0.f; }

    for (int kt = 0; kt < D_MODEL; kt += 16) {
        float4 av = axp ? axp[(kt >> 2) + akq] : make_float4(0.f, 0.f, 0.f, 0.f);
        As[akq * 4 + 0][arow] = av.x;
        As[akq * 4 + 1][arow] = av.y;
        As[akq * 4 + 2][arow] = av.z;
        As[akq * 4 + 3][arow] = av.w;
#pragma unroll
        for (int l = 0; l < 2; l++) {
            int idx = tid + l * 256;
            int brow = idx >> 5, c4 = idx & 31;
            const float* gsrc = Wg + (size_t)(kt + brow) * D_FFN + n0 + c4 * 4;
            const float* usrc = Wu + (size_t)(kt + brow) * D_FFN + n0 + c4 * 4;
            *(float4*)&Bg[brow][c4 * 4] = *(const float4*)gsrc;
            *(float4*)&Bu[brow][c4 * 4] = *(const float4*)usrc;
        }
        __syncthreads();
#pragma unroll
        for (int k = 0; k < 16; k++) {
            float4 a4 = *(const float4*)&As[k][tm * 4];
            float4 g0 = *(const float4*)&Bg[k][tn * 8];
            float4 g1 = *(const float4*)&Bg[k][tn * 8 + 4];
            float4 u0 = *(const float4*)&Bu[k][tn * 8];
            float4 u1 = *(const float4*)&Bu[k][tn * 8 + 4];
            float aa[4] = {a4.x, a4.y, a4.z, a4.w};
            float gg[8] = {g0.x, g0.y, g0.z, g0.w, g1.x, g1.y, g1.z, g1.w};
            float uu[8] = {u0.x, u0.y, u0.z, u0.w, u1.x, u1.y, u1.z, u1.w};
#pragma unroll
            for (int i = 0; i < 4; i++)
#pragma unroll
                for (int j = 0; j < 8; j++) {
                    accg[i][j] += aa[i] * gg[j];
                    accu[i][j] += aa[i] * uu[j];
                }
        }
        __syncthreads();
    }
#pragma unroll
    for (int i = 0; i < 4; i++) {
        int r = r0 + tm * 4 + i;
        float* hp = H + (size_t)r * D_FFN + n0 + tn * 8;
#pragma unroll
        for (int j = 0; j < 8; j++) {
            float g = accg[i][j];
            float h = g * (1.f / (1.f + __expf(-g))) * accu[i][j];
            hp[j] = h;
        }
    }
}

// ---------------- K6/K8: down GEMM -------------------------------------------
// C tile: 128 x 128, K-step 16, 256 threads, 8x8 micro-tile per thread.
template <bool EXPERT>
__global__ void __launch_bounds__(256) down_kernel(
    const float* __restrict__ Hbuf, const float* __restrict__ Wd_base,
    float* __restrict__ out) {
    int by = blockIdx.y, bx = blockIdx.x;
    int te = 0;
    if (EXPERT) { te = g_tile_dn[by]; if (te < 0) return; }
    const float* Wd = Wd_base + (size_t)te * D_FFN * D_MODEL;
    int n0 = bx * 128, r0 = by * 128;

    __shared__ float As[16][128];
    __shared__ float Bs[16][128];

    int tid = threadIdx.x;
    int tm = tid >> 4, tn = tid & 15;
    float acc[8][8];
#pragma unroll
    for (int i = 0; i < 8; i++)
#pragma unroll
        for (int j = 0; j < 8; j++) acc[i][j] = 0.f;

    for (int kt = 0; kt < D_FFN; kt += 16) {
#pragma unroll
        for (int l = 0; l < 2; l++) {
            int idx = tid + l * 256;
            int arow = idx >> 2, akq = idx & 3;
            float4 av = *(const float4*)(Hbuf + (size_t)(r0 + arow) * D_FFN + kt + akq * 4);
            As[akq * 4 + 0][arow] = av.x;
            As[akq * 4 + 1][arow] = av.y;
            As[akq * 4 + 2][arow] = av.z;
            As[akq * 4 + 3][arow] = av.w;
            int brow = idx >> 5, c4 = idx & 31;
            *(float4*)&Bs[brow][c4 * 4] =
                *(const float4*)(Wd + (size_t)(kt + brow) * D_MODEL + n0 + c4 * 4);
        }
        __syncthreads();
#pragma unroll
        for (int k = 0; k < 16; k++) {
            float4 a0 = *(const float4*)&As[k][tm * 8];
            float4 a1 = *(const float4*)&As[k][tm * 8 + 4];
            float4 b0 = *(const float4*)&Bs[k][tn * 8];
            float4 b1 = *(const float4*)&Bs[k][tn * 8 + 4];
            float aa[8] = {a0.x, a0.y, a0.z, a0.w, a1.x, a1.y, a1.z, a1.w};
            float bb[8] = {b0.x, b0.y, b0.z, b0.w, b1.x, b1.y, b1.z, b1.w};
#pragma unroll
            for (int i = 0; i < 8; i++)
#pragma unroll
                for (int j = 0; j < 8; j++) acc[i][j] += aa[i] * bb[j];
        }
        __syncthreads();
    }

    if (EXPERT) {
#pragma unroll
        for (int i = 0; i < 8; i++) {
            int r = r0 + tm * 8 + i;
            int tok = g_slot_token[r];
            if (tok < 0) continue;
            float w = g_slot_w[r];
            float* op = out + (size_t)tok * D_MODEL + n0 + tn * 8;
#pragma unroll
            for (int j = 0; j < 8; j++) atomicAdd(&op[j], w * acc[i][j]);
        }
    } else {
#pragma unroll
        for (int i = 0; i < 8; i++) {
            int r = r0 + tm * 8 + i;
            float* op = out + (size_t)r * D_MODEL + n0 + tn * 8;
#pragma unroll
            for (int j = 0; j < 8; j++) op[j] = acc[i][j];
        }
    }
}

// ---------------- launch ------------------------------------------------------
extern "C" void kernel_launch(void* const* d_in, const int* in_sizes, int n_in,
                              void* d_out, int out_size) {
    const float* x         = (const float*)d_in[0];
    const float* shared_wg = (const float*)d_in[1];
    const float* shared_wu = (const float*)d_in[2];
    const float* shared_wd = (const float*)d_in[3];
    const float* exp_wg    = (const float*)d_in[4];
    const float* exp_wu    = (const float*)d_in[5];
    const float* exp_wd    = (const float*)d_in[6];
    const float* router_w  = (const float*)d_in[7];
    float* out = (float*)d_out;

    float* Hshared; cudaGetSymbolAddress((void**)&Hshared, g_Hshared);
    float* Hexp;    cudaGetSymbolAddress((void**)&Hexp, g_Hexp);

    init_kernel<<<(MAXSLOT + 255) / 256, 256>>>();
    router_kernel<<<N_TOK / 4, 128>>>(x, router_w);
    offsets_kernel<<<1, 128>>>(out, out_size);
    scatter_kernel<<<N_TOK / 256, 256>>>();

    // shared expert
    gateup_kernel<false><<<dim3(D_FFN / 128, N_TOK / 64), 256>>>(
        x, shared_wg, shared_wu, Hshared);
    down_kernel<false><<<dim3(D_MODEL / 128, N_TOK / 128), 256>>>(
        Hshared, shared_wd, out);

    // routed experts (gathered)
    gateup_kernel<true><<<dim3(D_FFN / 128, NT_GU), 256>>>(
        x, exp_wg, exp_wu, Hexp);
    down_kernel<true><<<dim3(D_MODEL / 128, NT_DN), 256>>>(
        Hexp, exp_wd, out);
}

// round 5
// speedup vs baseline: 2.4370x; 2.4314x over previous
#include <cuda_runtime.h>
#include <cuda_bf16.h>
#include <math.h>
#include <stdint.h>

#define D_MODEL 1024
#define D_FFN   2048
#define N_TOK   4096
#define N_EXP   8
#define MAXSLOT 9216
#define NT_DN   (MAXSLOT / 128)

#define GU_SMEM 40960   /* A 2*10240 + Bg 2*5120 + Bu 2*5120 */
#define DN_SMEM 30720   /* A 2*10240 + B 2*5120              */

// ---------------- scratch ----------------------------------------------------
__device__ __nv_bfloat16 g_Xhi[(size_t)N_TOK * D_MODEL];
__device__ __nv_bfloat16 g_Xlo[(size_t)N_TOK * D_MODEL];
__device__ __nv_bfloat16 g_Bg_hi[(size_t)9 * D_FFN * D_MODEL];
__device__ __nv_bfloat16 g_Bg_lo[(size_t)9 * D_FFN * D_MODEL];
__device__ __nv_bfloat16 g_Bu_hi[(size_t)9 * D_FFN * D_MODEL];
__device__ __nv_bfloat16 g_Bu_lo[(size_t)9 * D_FFN * D_MODEL];
__device__ __nv_bfloat16 g_Bd_hi[(size_t)9 * D_MODEL * D_FFN];
__device__ __nv_bfloat16 g_Bd_lo[(size_t)9 * D_MODEL * D_FFN];
__device__ __nv_bfloat16 g_Hs_hi[(size_t)N_TOK * D_FFN];
__device__ __nv_bfloat16 g_Hs_lo[(size_t)N_TOK * D_FFN];
__device__ __nv_bfloat16 g_He_hi[(size_t)MAXSLOT * D_FFN];
__device__ __nv_bfloat16 g_He_lo[(size_t)MAXSLOT * D_FFN];
__device__ int   g_slot_token[MAXSLOT];
__device__ float g_slot_w[MAXSLOT];
__device__ int   g_counts[N_EXP];
__device__ float g_psum[N_EXP];
__device__ int   g_fill[N_EXP];
__device__ int   g_padoff[N_EXP + 1];
__device__ int   g_tile_dn[NT_DN];
__device__ int   g_tok_idx[N_TOK * 2];
__device__ float g_tok_w[N_TOK * 2];

// ---------------- PTX helpers (all valid on plain sm_103 target) --------------
__device__ __forceinline__ uint32_t s2u(const void* p) {
    return (uint32_t)__cvta_generic_to_shared(p);
}
__device__ __forceinline__ void cpa16(uint32_t dst, const void* src) {
    asm volatile("cp.async.cg.shared.global [%0], [%1], 16;" :: "r"(dst), "l"(src));
}
__device__ __forceinline__ void cp_commit() {
    asm volatile("cp.async.commit_group;");
}
template <int N>
__device__ __forceinline__ void cp_wait() {
    asm volatile("cp.async.wait_group %0;" :: "n"(N));
}
__device__ __forceinline__ void ldm4(uint32_t* r, uint32_t addr) {
    asm volatile("ldmatrix.sync.aligned.m8n8.x4.shared.b16 {%0,%1,%2,%3}, [%4];"
                 : "=r"(r[0]), "=r"(r[1]), "=r"(r[2]), "=r"(r[3]) : "r"(addr));
}
__device__ __forceinline__ void mma_bf16(float* c, const uint32_t* a,
                                         uint32_t b0, uint32_t b1) {
    asm volatile("mma.sync.aligned.m16n8k16.row.col.f32.bf16.bf16.f32 "
                 "{%0,%1,%2,%3}, {%4,%5,%6,%7}, {%8,%9}, {%0,%1,%2,%3};"
                 : "+f"(c[0]), "+f"(c[1]), "+f"(c[2]), "+f"(c[3])
                 : "r"(a[0]), "r"(a[1]), "r"(a[2]), "r"(a[3]), "r"(b0), "r"(b1));
}

// ---------------- routing kernels ---------------------------------------------
__global__ void init_kernel() {
    int i = blockIdx.x * blockDim.x + threadIdx.x;
    if (i < MAXSLOT) g_slot_token[i] = -1;
    if (i < N_EXP) { g_counts[i] = 0; g_psum[i] = 0.f; g_fill[i] = 0; }
}

__global__ void router_kernel(const float* __restrict__ x,
                              const float* __restrict__ rw) {
    int t = blockIdx.x * 4 + (threadIdx.x >> 5);
    int lane = threadIdx.x & 31;
    if (t >= N_TOK) return;
    const float* xr = x + (size_t)t * D_MODEL;
    float acc[N_EXP];
#pragma unroll
    for (int e = 0; e < N_EXP; e++) acc[e] = 0.f;
    for (int k = lane; k < D_MODEL; k += 32) {
        float xv = xr[k];
#pragma unroll
        for (int e = 0; e < N_EXP; e++) acc[e] += xv * rw[k * N_EXP + e];
    }
#pragma unroll
    for (int e = 0; e < N_EXP; e++)
#pragma unroll
        for (int o = 16; o; o >>= 1) acc[e] += __shfl_xor_sync(0xffffffffu, acc[e], o);
    if (lane == 0) {
        int i0 = 0; float v0 = acc[0];
#pragma unroll
        for (int e = 1; e < N_EXP; e++) if (acc[e] > v0) { v0 = acc[e]; i0 = e; }
        int i1 = -1; float v1 = -1e30f;
#pragma unroll
        for (int e = 0; e < N_EXP; e++) {
            if (e == i0) continue;
            if (acc[e] > v1) { v1 = acc[e]; i1 = e; }
        }
        float m2 = fmaxf(v0, v1);
        float e0 = expf(v0 - m2), e1 = expf(v1 - m2);
        float inv = 1.f / (e0 + e1);
        g_tok_idx[t * 2 + 0] = i0;  g_tok_w[t * 2 + 0] = e0 * inv;
        g_tok_idx[t * 2 + 1] = i1;  g_tok_w[t * 2 + 1] = e1 * inv;
        atomicAdd(&g_counts[i0], 1);
        atomicAdd(&g_counts[i1], 1);
        float mm = acc[0];
#pragma unroll
        for (int e = 1; e < N_EXP; e++) mm = fmaxf(mm, acc[e]);
        float s = 0.f, ex[N_EXP];
#pragma unroll
        for (int e = 0; e < N_EXP; e++) { ex[e] = expf(acc[e] - mm); s += ex[e]; }
        float invs = 1.f / s;
#pragma unroll
        for (int e = 0; e < N_EXP; e++) atomicAdd(&g_psum[e], ex[e] * invs);
    }
}

__global__ void offsets_kernel(float* __restrict__ out, int out_size) {
    __shared__ int spad[N_EXP + 1];
    int tid = threadIdx.x;
    if (tid == 0) {
        int off = 0;
        for (int e = 0; e < N_EXP; e++) {
            g_padoff[e] = off;
            off += ((g_counts[e] + 127) / 128) * 128;
        }
        g_padoff[N_EXP] = off;
        for (int e = 0; e <= N_EXP; e++) spad[e] = g_padoff[e];
        double s = 0.0;
        for (int e = 0; e < N_EXP; e++) s += (double)g_counts[e] * (double)g_psum[e];
        float aux = (float)((double)N_EXP * s / ((double)N_TOK * (double)N_TOK));
        if (out_size > N_TOK * D_MODEL) out[(size_t)N_TOK * D_MODEL] = aux;
    }
    __syncthreads();
    for (int j = tid; j < NT_DN; j += blockDim.x) {
        int row = j * 128, te = -1;
#pragma unroll
        for (int e = 0; e < N_EXP; e++)
            if (row >= spad[e] && row < spad[e + 1]) te = e;
        g_tile_dn[j] = te;
    }
}

__global__ void scatter_kernel() {
    int t = blockIdx.x * blockDim.x + threadIdx.x;
    if (t >= N_TOK) return;
#pragma unroll
    for (int k = 0; k < 2; k++) {
        int e = g_tok_idx[t * 2 + k];
        float w = g_tok_w[t * 2 + k];
        int pos = atomicAdd(&g_fill[e], 1);
        int slot = g_padoff[e] + pos;
        g_slot_token[slot] = t;
        g_slot_w[slot] = w;
    }
}

// ---------------- conversions --------------------------------------------------
__global__ void conv_x_kernel(const float* __restrict__ x) {
    int i = blockIdx.x * 256 + threadIdx.x;
    float v = x[i];
    __nv_bfloat16 h = __float2bfloat16(v);
    g_Xhi[i] = h;
    g_Xlo[i] = __float2bfloat16(v - __bfloat162float(h));
}

// transpose [R,C] fp32 -> [slab][C][R] bf16 hi/lo
__global__ void conv_w_kernel(const float* __restrict__ srcS, const float* __restrict__ srcE,
                              __nv_bfloat16* __restrict__ hiO, __nv_bfloat16* __restrict__ loO,
                              int R, int C) {
    int slab = blockIdx.z;
    const float* src = (slab == 0) ? srcS : srcE + (size_t)(slab - 1) * R * C;
    size_t ob = (size_t)slab * R * C;
    __shared__ float t[32][33];
    int tx = threadIdx.x & 31, ty = threadIdx.x >> 5;
    int r0 = blockIdx.y * 32, c0 = blockIdx.x * 32;
#pragma unroll
    for (int p = 0; p < 4; p++)
        t[p * 8 + ty][tx] = src[(size_t)(r0 + p * 8 + ty) * C + c0 + tx];
    __syncthreads();
#pragma unroll
    for (int p = 0; p < 4; p++) {
        int n = c0 + p * 8 + ty, k = r0 + tx;
        float v = t[tx][p * 8 + ty];
        __nv_bfloat16 h = __float2bfloat16(v);
        hiO[ob + (size_t)n * R + k] = h;
        loO[ob + (size_t)n * R + k] = __float2bfloat16(v - __bfloat162float(h));
    }
}

// ---------------- fused gate+up GEMM (mma.sync) + SwiGLU ------------------------
// Block tile 128M x 64N, K-step 32, 8 warps (4M x 2N), warp tile 32x32.
template <bool EXPERT>
__global__ void __launch_bounds__(256) mma_gateup_kernel() {
    const int by = blockIdx.y;
    int te = 0;
    if (EXPERT) { te = g_tile_dn[by]; if (te < 0) return; }
    const int slab = EXPERT ? 1 + te : 0;
    const int n0 = blockIdx.x * 64, r0 = by * 128;
    const int tid = threadIdx.x, lane = tid & 31, wid = tid >> 5;
    const int wm = wid & 3, wn = wid >> 2;

    extern __shared__ __align__(16) char smem[];
    __shared__ int stok[128];
    const uint32_t sbase = s2u(smem);

    if (tid < 128) {
        if (EXPERT) { int t = g_slot_token[r0 + tid]; stok[tid] = t < 0 ? 0 : t; }
        else        stok[tid] = r0 + tid;
    }
    __syncthreads();

    const size_t slaboff = (size_t)slab * D_FFN * D_MODEL;

    auto load_stage = [&](int s) {
        const int p = s >> 5, k0 = (s & 31) << 5, b = s & 1;
        const __nv_bfloat16* __restrict__ Ab = (p == 2) ? g_Xlo : g_Xhi;
        const __nv_bfloat16* __restrict__ Gb = ((p == 1) ? g_Bg_lo : g_Bg_hi) + slaboff;
        const __nv_bfloat16* __restrict__ Ub = ((p == 1) ? g_Bu_lo : g_Bu_hi) + slaboff;
        uint32_t Ad = sbase + b * 10240;
        uint32_t Gd = sbase + 20480 + b * 5120;
        uint32_t Ud = sbase + 30720 + b * 5120;
#pragma unroll
        for (int it = 0; it < 2; it++) {
            int idx = tid + it * 256;
            int row = idx >> 2, ch = idx & 3;
            cpa16(Ad + row * 80 + ch * 16,
                  Ab + (size_t)stok[row] * D_MODEL + k0 + ch * 8);
        }
        {
            int row = tid >> 2, ch = tid & 3;
            size_t o = (size_t)(n0 + row) * D_MODEL + k0 + ch * 8;
            cpa16(Gd + row * 80 + ch * 16, Gb + o);
            cpa16(Ud + row * 80 + ch * 16, Ub + o);
        }
        cp_commit();
    };

    float ag[2][4][4] = {}, au[2][4][4] = {};

    load_stage(0);
    for (int s = 0; s < 96; s++) {
        if (s + 1 < 96) { load_stage(s + 1); cp_wait<1>(); }
        else            cp_wait<0>();
        __syncthreads();
        const int b = s & 1;
        const uint32_t Ab = sbase + b * 10240;
        const uint32_t Gb = sbase + 20480 + b * 5120;
        const uint32_t Ub = sbase + 30720 + b * 5120;
        const int lr = lane & 15, lc = (lane >> 4) * 16;
#pragma unroll
        for (int kh = 0; kh < 2; kh++) {
            const int kb = kh * 32 + lc;
            uint32_t af[2][4], bg[2][4], bu[2][4];
#pragma unroll
            for (int mi = 0; mi < 2; mi++)
                ldm4(af[mi], Ab + (wm * 32 + mi * 16 + lr) * 80 + kb);
#pragma unroll
            for (int nj = 0; nj < 2; nj++) {
                uint32_t ro = (wn * 32 + nj * 16 + lr) * 80 + kb;
                ldm4(bg[nj], Gb + ro);
                ldm4(bu[nj], Ub + ro);
            }
#pragma unroll
            for (int mi = 0; mi < 2; mi++)
#pragma unroll
                for (int nj = 0; nj < 2; nj++) {
                    mma_bf16(ag[mi][nj * 2],     af[mi], bg[nj][0], bg[nj][2]);
                    mma_bf16(ag[mi][nj * 2 + 1], af[mi], bg[nj][1], bg[nj][3]);
                    mma_bf16(au[mi][nj * 2],     af[mi], bu[nj][0], bu[nj][2]);
                    mma_bf16(au[mi][nj * 2 + 1], af[mi], bu[nj][1], bu[nj][3]);
                }
        }
        __syncthreads();
    }

    __nv_bfloat16* __restrict__ Hhi = EXPERT ? g_He_hi : g_Hs_hi;
    __nv_bfloat16* __restrict__ Hlo = EXPERT ? g_He_lo : g_Hs_lo;
#pragma unroll
    for (int mi = 0; mi < 2; mi++)
#pragma unroll
        for (int ni = 0; ni < 4; ni++) {
            int rl = wm * 32 + mi * 16 + (lane >> 2);
            int cl = n0 + wn * 32 + ni * 8 + 2 * (lane & 3);
#pragma unroll
            for (int hh = 0; hh < 2; hh++) {
                int r = r0 + rl + hh * 8;
                float g0 = ag[mi][ni][hh * 2],     u0 = au[mi][ni][hh * 2];
                float g1 = ag[mi][ni][hh * 2 + 1], u1 = au[mi][ni][hh * 2 + 1];
                float h0 = g0 / (1.f + expf(-g0)) * u0;
                float h1 = g1 / (1.f + expf(-g1)) * u1;
                __nv_bfloat16 h0h = __float2bfloat16(h0);
                __nv_bfloat16 h1h = __float2bfloat16(h1);
                __nv_bfloat162 hv; hv.x = h0h; hv.y = h1h;
                __nv_bfloat162 lv;
                lv.x = __float2bfloat16(h0 - __bfloat162float(h0h));
                lv.y = __float2bfloat16(h1 - __bfloat162float(h1h));
                *(__nv_bfloat162*)(Hhi + (size_t)r * D_FFN + cl) = hv;
                *(__nv_bfloat162*)(Hlo + (size_t)r * D_FFN + cl) = lv;
            }
        }
}

// ---------------- down GEMM (mma.sync) ------------------------------------------
template <bool EXPERT>
__global__ void __launch_bounds__(256) mma_down_kernel(float* __restrict__ out) {
    const int by = blockIdx.y;
    int te = 0;
    if (EXPERT) { te = g_tile_dn[by]; if (te < 0) return; }
    const int slab = EXPERT ? 1 + te : 0;
    const int n0 = blockIdx.x * 64, r0 = by * 128;
    const int tid = threadIdx.x, lane = tid & 31, wid = tid >> 5;
    const int wm = wid & 3, wn = wid >> 2;

    extern __shared__ __align__(16) char smem[];
    const uint32_t sbase = s2u(smem);
    const size_t slaboff = (size_t)slab * D_MODEL * D_FFN;

    auto load_stage = [&](int s) {
        const int p = s >> 6, k0 = (s & 63) << 5, b = s & 1;
        const __nv_bfloat16* __restrict__ Ab =
            EXPERT ? ((p == 2) ? g_He_lo : g_He_hi) : ((p == 2) ? g_Hs_lo : g_Hs_hi);
        const __nv_bfloat16* __restrict__ Bb = ((p == 1) ? g_Bd_lo : g_Bd_hi) + slaboff;
        uint32_t Ad = sbase + b * 10240;
        uint32_t Bd = sbase + 20480 + b * 5120;
#pragma unroll
        for (int it = 0; it < 2; it++) {
            int idx = tid + it * 256;
            int row = idx >> 2, ch = idx & 3;
            cpa16(Ad + row * 80 + ch * 16,
                  Ab + (size_t)(r0 + row) * D_FFN + k0 + ch * 8);
        }
        {
            int row = tid >> 2, ch = tid & 3;
            cpa16(Bd + row * 80 + ch * 16,
                  Bb + (size_t)(n0 + row) * D_FFN + k0 + ch * 8);
        }
        cp_commit();
    };

    float ac[2][4][4] = {};

    load_stage(0);
    for (int s = 0; s < 192; s++) {
        if (s + 1 < 192) { load_stage(s + 1); cp_wait<1>(); }
        else             cp_wait<0>();
        __syncthreads();
        const int b = s & 1;
        const uint32_t Ab = sbase + b * 10240;
        const uint32_t Bb = sbase + 20480 + b * 5120;
        const int lr = lane & 15, lc = (lane >> 4) * 16;
#pragma unroll
        for (int kh = 0; kh < 2; kh++) {
            const int kb = kh * 32 + lc;
            uint32_t af[2][4], bf[2][4];
#pragma unroll
            for (int mi = 0; mi < 2; mi++)
                ldm4(af[mi], Ab + (wm * 32 + mi * 16 + lr) * 80 + kb);
#pragma unroll
            for (int nj = 0; nj < 2; nj++)
                ldm4(bf[nj], Bb + (wn * 32 + nj * 16 + lr) * 80 + kb);
#pragma unroll
            for (int mi = 0; mi < 2; mi++)
#pragma unroll
                for (int nj = 0; nj < 2; nj++) {
                    mma_bf16(ac[mi][nj * 2],     af[mi], bf[nj][0], bf[nj][2]);
                    mma_bf16(ac[mi][nj * 2 + 1], af[mi], bf[nj][1], bf[nj][3]);
                }
        }
        __syncthreads();
    }

#pragma unroll
    for (int mi = 0; mi < 2; mi++)
#pragma unroll
        for (int ni = 0; ni < 4; ni++) {
            int rl = wm * 32 + mi * 16 + (lane >> 2);
            int cl = n0 + wn * 32 + ni * 8 + 2 * (lane & 3);
#pragma unroll
            for (int hh = 0; hh < 2; hh++) {
                int slot = r0 + rl + hh * 8;
                float c0 = ac[mi][ni][hh * 2], c1 = ac[mi][ni][hh * 2 + 1];
                if (EXPERT) {
                    int tok = g_slot_token[slot];
                    if (tok >= 0) {
                        float w = g_slot_w[slot];
                        float* op = out + (size_t)tok * D_MODEL + cl;
                        atomicAdd(&op[0], w * c0);
                        atomicAdd(&op[1], w * c1);
                    }
                } else {
                    float2 v; v.x = c0; v.y = c1;
                    *(float2*)(out + (size_t)slot * D_MODEL + cl) = v;
                }
            }
        }
}

// ---------------- launch ----------------------------------------------------------
extern "C" void kernel_launch(void* const* d_in, const int* in_sizes, int n_in,
                              void* d_out, int out_size) {
    const float* x         = (const float*)d_in[0];
    const float* shared_wg = (const float*)d_in[1];
    const float* shared_wu = (const float*)d_in[2];
    const float* shared_wd = (const float*)d_in[3];
    const float* exp_wg    = (const float*)d_in[4];
    const float* exp_wu    = (const float*)d_in[5];
    const float* exp_wd    = (const float*)d_in[6];
    const float* router_w  = (const float*)d_in[7];
    float* out = (float*)d_out;

    // FIX (R4 bug): __device__ symbols must be resolved to device addresses
    // before being passed as kernel arguments. Passing the symbol directly
    // from host code hands the kernel the host shadow address (silently
    // "working" via ATS on GB300), leaving the real buffers zero.
    __nv_bfloat16 *bg_hi, *bg_lo, *bu_hi, *bu_lo, *bd_hi, *bd_lo;
    cudaGetSymbolAddress((void**)&bg_hi, g_Bg_hi);
    cudaGetSymbolAddress((void**)&bg_lo, g_Bg_lo);
    cudaGetSymbolAddress((void**)&bu_hi, g_Bu_hi);
    cudaGetSymbolAddress((void**)&bu_lo, g_Bu_lo);
    cudaGetSymbolAddress((void**)&bd_hi, g_Bd_hi);
    cudaGetSymbolAddress((void**)&bd_lo, g_Bd_lo);

    init_kernel<<<(MAXSLOT + 255) / 256, 256>>>();
    router_kernel<<<N_TOK / 4, 128>>>(x, router_w);
    offsets_kernel<<<1, 128>>>(out, out_size);
    scatter_kernel<<<N_TOK / 256, 256>>>();

    conv_x_kernel<<<(N_TOK * D_MODEL) / 256, 256>>>(x);
    conv_w_kernel<<<dim3(D_FFN / 32, D_MODEL / 32, 9), 256>>>(
        shared_wg, exp_wg, bg_hi, bg_lo, D_MODEL, D_FFN);
    conv_w_kernel<<<dim3(D_FFN / 32, D_MODEL / 32, 9), 256>>>(
        shared_wu, exp_wu, bu_hi, bu_lo, D_MODEL, D_FFN);
    conv_w_kernel<<<dim3(D_MODEL / 32, D_FFN / 32, 9), 256>>>(
        shared_wd, exp_wd, bd_hi, bd_lo, D_FFN, D_MODEL);

    mma_gateup_kernel<false><<<dim3(D_FFN / 64, N_TOK / 128), 256, GU_SMEM>>>();
    mma_gateup_kernel<true><<<dim3(D_FFN / 64, NT_DN), 256, GU_SMEM>>>();
    mma_down_kernel<false><<<dim3(D_MODEL / 64, N_TOK / 128), 256, DN_SMEM>>>(out);
    mma_down_kernel<true><<<dim3(D_MODEL / 64, NT_DN), 256, DN_SMEM>>>(out);
}

// round 6
// speedup vs baseline: 2.5672x; 1.0534x over previous
#include <cuda_runtime.h>
#include <cuda_bf16.h>
#include <math.h>
#include <stdint.h>

#define D_MODEL 1024
#define D_FFN   2048
#define N_TOK   4096
#define N_EXP   8
#define MAXSLOT 9216
#define NT_SH   (N_TOK / 128)     /* 32 shared row tiles */
#define NT_DN   (MAXSLOT / 128)   /* 72 expert row tiles */

#define GU_STG  20480             /* A 10240 + G 5120 + U 5120 */
#define DN_STG  15360             /* A 10240 + B 5120          */
#define GU_SMEM (4 * GU_STG)      /* 81920 */
#define DN_SMEM (4 * DN_STG)      /* 61440 */

// ---------------- scratch ----------------------------------------------------
__device__ __nv_bfloat16 g_Xhi[(size_t)N_TOK * D_MODEL];
__device__ __nv_bfloat16 g_Xlo[(size_t)N_TOK * D_MODEL];
__device__ __nv_bfloat16 g_Bg_hi[(size_t)9 * D_FFN * D_MODEL];
__device__ __nv_bfloat16 g_Bg_lo[(size_t)9 * D_FFN * D_MODEL];
__device__ __nv_bfloat16 g_Bu_hi[(size_t)9 * D_FFN * D_MODEL];
__device__ __nv_bfloat16 g_Bu_lo[(size_t)9 * D_FFN * D_MODEL];
__device__ __nv_bfloat16 g_Bd_hi[(size_t)9 * D_MODEL * D_FFN];
__device__ __nv_bfloat16 g_Bd_lo[(size_t)9 * D_MODEL * D_FFN];
__device__ __nv_bfloat16 g_Hs_hi[(size_t)N_TOK * D_FFN];
__device__ __nv_bfloat16 g_Hs_lo[(size_t)N_TOK * D_FFN];
__device__ __nv_bfloat16 g_He_hi[(size_t)MAXSLOT * D_FFN];
__device__ __nv_bfloat16 g_He_lo[(size_t)MAXSLOT * D_FFN];
__device__ float g_Os[(size_t)N_TOK * D_MODEL];
__device__ float g_Oe[(size_t)MAXSLOT * D_MODEL];
__device__ int   g_slot_token[MAXSLOT];
__device__ int   g_counts[N_EXP];
__device__ float g_psum[N_EXP];
__device__ int   g_fill[N_EXP];
__device__ int   g_padoff[N_EXP + 1];
__device__ int   g_tile_dn[NT_DN];
__device__ int   g_tok_idx[N_TOK * 2];
__device__ int   g_tok_slot[N_TOK * 2];
__device__ float g_tok_w[N_TOK * 2];

// ---------------- PTX helpers -------------------------------------------------
__device__ __forceinline__ uint32_t s2u(const void* p) {
    return (uint32_t)__cvta_generic_to_shared(p);
}
__device__ __forceinline__ void cpa16(uint32_t dst, const void* src) {
    asm volatile("cp.async.cg.shared.global [%0], [%1], 16;" :: "r"(dst), "l"(src));
}
__device__ __forceinline__ void cp_commit() {
    asm volatile("cp.async.commit_group;");
}
template <int N>
__device__ __forceinline__ void cp_wait() {
    asm volatile("cp.async.wait_group %0;" :: "n"(N));
}
__device__ __forceinline__ void ldm4(uint32_t* r, uint32_t addr) {
    asm volatile("ldmatrix.sync.aligned.m8n8.x4.shared.b16 {%0,%1,%2,%3}, [%4];"
                 : "=r"(r[0]), "=r"(r[1]), "=r"(r[2]), "=r"(r[3]) : "r"(addr));
}
__device__ __forceinline__ void mma_bf16(float* c, const uint32_t* a,
                                         uint32_t b0, uint32_t b1) {
    asm volatile("mma.sync.aligned.m16n8k16.row.col.f32.bf16.bf16.f32 "
                 "{%0,%1,%2,%3}, {%4,%5,%6,%7}, {%8,%9}, {%0,%1,%2,%3};"
                 : "+f"(c[0]), "+f"(c[1]), "+f"(c[2]), "+f"(c[3])
                 : "r"(a[0]), "r"(a[1]), "r"(a[2]), "r"(a[3]), "r"(b0), "r"(b1));
}

// ---------------- routing kernels ---------------------------------------------
__global__ void init_kernel() {
    int i = blockIdx.x * blockDim.x + threadIdx.x;
    if (i < MAXSLOT) g_slot_token[i] = -1;
    if (i < N_EXP) { g_counts[i] = 0; g_psum[i] = 0.f; g_fill[i] = 0; }
}

__global__ void router_kernel(const float* __restrict__ x,
                              const float* __restrict__ rw) {
    int t = blockIdx.x * 4 + (threadIdx.x >> 5);
    int lane = threadIdx.x & 31;
    if (t >= N_TOK) return;
    const float* xr = x + (size_t)t * D_MODEL;
    float acc[N_EXP];
#pragma unroll
    for (int e = 0; e < N_EXP; e++) acc[e] = 0.f;
    for (int k = lane; k < D_MODEL; k += 32) {
        float xv = xr[k];
#pragma unroll
        for (int e = 0; e < N_EXP; e++) acc[e] += xv * rw[k * N_EXP + e];
    }
#pragma unroll
    for (int e = 0; e < N_EXP; e++)
#pragma unroll
        for (int o = 16; o; o >>= 1) acc[e] += __shfl_xor_sync(0xffffffffu, acc[e], o);
    if (lane == 0) {
        int i0 = 0; float v0 = acc[0];
#pragma unroll
        for (int e = 1; e < N_EXP; e++) if (acc[e] > v0) { v0 = acc[e]; i0 = e; }
        int i1 = -1; float v1 = -1e30f;
#pragma unroll
        for (int e = 0; e < N_EXP; e++) {
            if (e == i0) continue;
            if (acc[e] > v1) { v1 = acc[e]; i1 = e; }
        }
        float m2 = fmaxf(v0, v1);
        float e0 = expf(v0 - m2), e1 = expf(v1 - m2);
        float inv = 1.f / (e0 + e1);
        g_tok_idx[t * 2 + 0] = i0;  g_tok_w[t * 2 + 0] = e0 * inv;
        g_tok_idx[t * 2 + 1] = i1;  g_tok_w[t * 2 + 1] = e1 * inv;
        atomicAdd(&g_counts[i0], 1);
        atomicAdd(&g_counts[i1], 1);
        float mm = acc[0];
#pragma unroll
        for (int e = 1; e < N_EXP; e++) mm = fmaxf(mm, acc[e]);
        float s = 0.f, ex[N_EXP];
#pragma unroll
        for (int e = 0; e < N_EXP; e++) { ex[e] = expf(acc[e] - mm); s += ex[e]; }
        float invs = 1.f / s;
#pragma unroll
        for (int e = 0; e < N_EXP; e++) atomicAdd(&g_psum[e], ex[e] * invs);
    }
}

__global__ void offsets_kernel(float* __restrict__ out, int out_size) {
    __shared__ int spad[N_EXP + 1];
    int tid = threadIdx.x;
    if (tid == 0) {
        int off = 0;
        for (int e = 0; e < N_EXP; e++) {
            g_padoff[e] = off;
            off += ((g_counts[e] + 127) / 128) * 128;
        }
        g_padoff[N_EXP] = off;
        for (int e = 0; e <= N_EXP; e++) spad[e] = g_padoff[e];
        double s = 0.0;
        for (int e = 0; e < N_EXP; e++) s += (double)g_counts[e] * (double)g_psum[e];
        float aux = (float)((double)N_EXP * s / ((double)N_TOK * (double)N_TOK));
        if (out_size > N_TOK * D_MODEL) out[(size_t)N_TOK * D_MODEL] = aux;
    }
    __syncthreads();
    for (int j = tid; j < NT_DN; j += blockDim.x) {
        int row = j * 128, te = -1;
#pragma unroll
        for (int e = 0; e < N_EXP; e++)
            if (row >= spad[e] && row < spad[e + 1]) te = e;
        g_tile_dn[j] = te;
    }
}

__global__ void scatter_kernel() {
    int t = blockIdx.x * blockDim.x + threadIdx.x;
    if (t >= N_TOK) return;
#pragma unroll
    for (int k = 0; k < 2; k++) {
        int e = g_tok_idx[t * 2 + k];
        int pos = atomicAdd(&g_fill[e], 1);
        int slot = g_padoff[e] + pos;
        g_slot_token[slot] = t;
        g_tok_slot[t * 2 + k] = slot;
    }
}

// ---------------- conversions --------------------------------------------------
__global__ void conv_x_kernel(const float* __restrict__ x) {
    int i = blockIdx.x * 256 + threadIdx.x;
    float v = x[i];
    __nv_bfloat16 h = __float2bfloat16(v);
    g_Xhi[i] = h;
    g_Xlo[i] = __float2bfloat16(v - __bfloat162float(h));
}

__global__ void conv_w_kernel(const float* __restrict__ srcS, const float* __restrict__ srcE,
                              __nv_bfloat16* __restrict__ hiO, __nv_bfloat16* __restrict__ loO,
                              int R, int C) {
    int slab = blockIdx.z;
    const float* src = (slab == 0) ? srcS : srcE + (size_t)(slab - 1) * R * C;
    size_t ob = (size_t)slab * R * C;
    __shared__ float t[32][33];
    int tx = threadIdx.x & 31, ty = threadIdx.x >> 5;
    int r0 = blockIdx.y * 32, c0 = blockIdx.x * 32;
#pragma unroll
    for (int p = 0; p < 4; p++)
        t[p * 8 + ty][tx] = src[(size_t)(r0 + p * 8 + ty) * C + c0 + tx];
    __syncthreads();
#pragma unroll
    for (int p = 0; p < 4; p++) {
        int n = c0 + p * 8 + ty, k = r0 + tx;
        float v = t[tx][p * 8 + ty];
        __nv_bfloat16 h = __float2bfloat16(v);
        hiO[ob + (size_t)n * R + k] = h;
        loO[ob + (size_t)n * R + k] = __float2bfloat16(v - __bfloat162float(h));
    }
}

// ---------------- merged gate+up GEMM + SwiGLU ----------------------------------
// Block tile 128M x 64N, K-step 32, 8 warps (4M x 2N). 4-stage cp.async ring.
__global__ void __launch_bounds__(256) mma_gateup_kernel() {
    const int by = blockIdx.y;
    const bool sh = (by < NT_SH);
    int te = 0, r0;
    if (sh) r0 = by * 128;
    else {
        int be = by - NT_SH;
        te = g_tile_dn[be];
        if (te < 0) return;
        r0 = be * 128;
    }
    const int slab = sh ? 0 : 1 + te;
    const int n0 = blockIdx.x * 64;
    const int tid = threadIdx.x, lane = tid & 31, wid = tid >> 5;
    const int wm = wid & 3, wn = wid >> 2;

    extern __shared__ __align__(16) char smem[];
    __shared__ int stok[128];
    const uint32_t sbase = s2u(smem);

    if (tid < 128) {
        if (sh) stok[tid] = r0 + tid;
        else { int t = g_slot_token[r0 + tid]; stok[tid] = t < 0 ? 0 : t; }
    }
    __syncthreads();

    const size_t slaboff = (size_t)slab * D_FFN * D_MODEL;

    auto load_stage = [&](int s) {
        const int p = s >> 5, k0 = (s & 31) << 5, slot = s & 3;
        const __nv_bfloat16* __restrict__ Ab = (p == 2) ? g_Xlo : g_Xhi;
        const __nv_bfloat16* __restrict__ Gb = ((p == 1) ? g_Bg_lo : g_Bg_hi) + slaboff;
        const __nv_bfloat16* __restrict__ Ub = ((p == 1) ? g_Bu_lo : g_Bu_hi) + slaboff;
        uint32_t Ad = sbase + slot * GU_STG;
        uint32_t Gd = Ad + 10240;
        uint32_t Ud = Ad + 15360;
#pragma unroll
        for (int it = 0; it < 2; it++) {
            int idx = tid + it * 256;
            int row = idx >> 2, ch = idx & 3;
            cpa16(Ad + row * 80 + ch * 16,
                  Ab + (size_t)stok[row] * D_MODEL + k0 + ch * 8);
        }
        {
            int row = tid >> 2, ch = tid & 3;
            size_t o = (size_t)(n0 + row) * D_MODEL + k0 + ch * 8;
            cpa16(Gd + row * 80 + ch * 16, Gb + o);
            cpa16(Ud + row * 80 + ch * 16, Ub + o);
        }
        cp_commit();
    };

    float ag[2][4][4] = {}, au[2][4][4] = {};

    load_stage(0); load_stage(1); load_stage(2);
    for (int s = 0; s < 96; s++) {
        cp_wait<2>();
        __syncthreads();
        if (s + 3 < 96) load_stage(s + 3); else cp_commit();
        const uint32_t Abase = sbase + (s & 3) * GU_STG;
        const uint32_t Gbase = Abase + 10240;
        const uint32_t Ubase = Abase + 15360;
        const int lr = lane & 15, lc = (lane >> 4) * 16;
#pragma unroll
        for (int kh = 0; kh < 2; kh++) {
            const int kb = kh * 32 + lc;
            uint32_t af[2][4], bg[2][4], bu[2][4];
#pragma unroll
            for (int mi = 0; mi < 2; mi++)
                ldm4(af[mi], Abase + (wm * 32 + mi * 16 + lr) * 80 + kb);
#pragma unroll
            for (int nj = 0; nj < 2; nj++) {
                uint32_t ro = (wn * 32 + nj * 16 + lr) * 80 + kb;
                ldm4(bg[nj], Gbase + ro);
                ldm4(bu[nj], Ubase + ro);
            }
#pragma unroll
            for (int mi = 0; mi < 2; mi++)
#pragma unroll
                for (int nj = 0; nj < 2; nj++) {
                    mma_bf16(ag[mi][nj * 2],     af[mi], bg[nj][0], bg[nj][2]);
                    mma_bf16(ag[mi][nj * 2 + 1], af[mi], bg[nj][1], bg[nj][3]);
                    mma_bf16(au[mi][nj * 2],     af[mi], bu[nj][0], bu[nj][2]);
                    mma_bf16(au[mi][nj * 2 + 1], af[mi], bu[nj][1], bu[nj][3]);
                }
        }
    }

    __nv_bfloat16* __restrict__ Hhi = sh ? g_Hs_hi : g_He_hi;
    __nv_bfloat16* __restrict__ Hlo = sh ? g_Hs_lo : g_He_lo;
#pragma unroll
    for (int mi = 0; mi < 2; mi++)
#pragma unroll
        for (int ni = 0; ni < 4; ni++) {
            int rl = wm * 32 + mi * 16 + (lane >> 2);
            int cl = n0 + wn * 32 + ni * 8 + 2 * (lane & 3);
#pragma unroll
            for (int hh = 0; hh < 2; hh++) {
                int r = r0 + rl + hh * 8;
                float g0 = ag[mi][ni][hh * 2],     u0 = au[mi][ni][hh * 2];
                float g1 = ag[mi][ni][hh * 2 + 1], u1 = au[mi][ni][hh * 2 + 1];
                float h0 = g0 / (1.f + expf(-g0)) * u0;
                float h1 = g1 / (1.f + expf(-g1)) * u1;
                __nv_bfloat16 h0h = __float2bfloat16(h0);
                __nv_bfloat16 h1h = __float2bfloat16(h1);
                __nv_bfloat162 hv; hv.x = h0h; hv.y = h1h;
                __nv_bfloat162 lv;
                lv.x = __float2bfloat16(h0 - __bfloat162float(h0h));
                lv.y = __float2bfloat16(h1 - __bfloat162float(h1h));
                *(__nv_bfloat162*)(Hhi + (size_t)r * D_FFN + cl) = hv;
                *(__nv_bfloat162*)(Hlo + (size_t)r * D_FFN + cl) = lv;
            }
        }
}

// ---------------- merged down GEMM ------------------------------------------------
__global__ void __launch_bounds__(256) mma_down_kernel() {
    const int by = blockIdx.y;
    const bool sh = (by < NT_SH);
    int te = 0, r0;
    if (sh) r0 = by * 128;
    else {
        int be = by - NT_SH;
        te = g_tile_dn[be];
        if (te < 0) return;
        r0 = be * 128;
    }
    const int slab = sh ? 0 : 1 + te;
    const int n0 = blockIdx.x * 64;
    const int tid = threadIdx.x, lane = tid & 31, wid = tid >> 5;
    const int wm = wid & 3, wn = wid >> 2;

    extern __shared__ __align__(16) char smem[];
    const uint32_t sbase = s2u(smem);
    const size_t slaboff = (size_t)slab * D_MODEL * D_FFN;

    auto load_stage = [&](int s) {
        const int p = s >> 6, k0 = (s & 63) << 5, slot = s & 3;
        const __nv_bfloat16* __restrict__ Ab =
            sh ? ((p == 2) ? g_Hs_lo : g_Hs_hi) : ((p == 2) ? g_He_lo : g_He_hi);
        const __nv_bfloat16* __restrict__ Bb = ((p == 1) ? g_Bd_lo : g_Bd_hi) + slaboff;
        uint32_t Ad = sbase + slot * DN_STG;
        uint32_t Bd = Ad + 10240;
#pragma unroll
        for (int it = 0; it < 2; it++) {
            int idx = tid + it * 256;
            int row = idx >> 2, ch = idx & 3;
            cpa16(Ad + row * 80 + ch * 16,
                  Ab + (size_t)(r0 + row) * D_FFN + k0 + ch * 8);
        }
        {
            int row = tid >> 2, ch = tid & 3;
            cpa16(Bd + row * 80 + ch * 16,
                  Bb + (size_t)(n0 + row) * D_FFN + k0 + ch * 8);
        }
        cp_commit();
    };

    float ac[2][4][4] = {};

    load_stage(0); load_stage(1); load_stage(2);
    for (int s = 0; s < 192; s++) {
        cp_wait<2>();
        __syncthreads();
        if (s + 3 < 192) load_stage(s + 3); else cp_commit();
        const uint32_t Abase = sbase + (s & 3) * DN_STG;
        const uint32_t Bbase = Abase + 10240;
        const int lr = lane & 15, lc = (lane >> 4) * 16;
#pragma unroll
        for (int kh = 0; kh < 2; kh++) {
            const int kb = kh * 32 + lc;
            uint32_t af[2][4], bf[2][4];
#pragma unroll
            for (int mi = 0; mi < 2; mi++)
                ldm4(af[mi], Abase + (wm * 32 + mi * 16 + lr) * 80 + kb);
#pragma unroll
            for (int nj = 0; nj < 2; nj++)
                ldm4(bf[nj], Bbase + (wn * 32 + nj * 16 + lr) * 80 + kb);
#pragma unroll
            for (int mi = 0; mi < 2; mi++)
#pragma unroll
                for (int nj = 0; nj < 2; nj++) {
                    mma_bf16(ac[mi][nj * 2],     af[mi], bf[nj][0], bf[nj][2]);
                    mma_bf16(ac[mi][nj * 2 + 1], af[mi], bf[nj][1], bf[nj][3]);
                }
        }
    }

    float* __restrict__ O = sh ? g_Os : g_Oe;
#pragma unroll
    for (int mi = 0; mi < 2; mi++)
#pragma unroll
        for (int ni = 0; ni < 4; ni++) {
            int rl = wm * 32 + mi * 16 + (lane >> 2);
            int cl = n0 + wn * 32 + ni * 8 + 2 * (lane & 3);
#pragma unroll
            for (int hh = 0; hh < 2; hh++) {
                int r = r0 + rl + hh * 8;
                float2 v;
                v.x = ac[mi][ni][hh * 2];
                v.y = ac[mi][ni][hh * 2 + 1];
                *(float2*)(O + (size_t)r * D_MODEL + cl) = v;
            }
        }
}

// ---------------- combine: out = Os + w0*Oe[s0] + w1*Oe[s1] -----------------------
__global__ void combine_kernel(float* __restrict__ out) {
    int t = blockIdx.x;
    int tid = threadIdx.x;
    int s0 = g_tok_slot[t * 2 + 0], s1 = g_tok_slot[t * 2 + 1];
    float w0 = g_tok_w[t * 2 + 0],  w1 = g_tok_w[t * 2 + 1];
    const float4* a = (const float4*)(g_Os + (size_t)t * D_MODEL) + tid;
    const float4* b = (const float4*)(g_Oe + (size_t)s0 * D_MODEL) + tid;
    const float4* c = (const float4*)(g_Oe + (size_t)s1 * D_MODEL) + tid;
    float4 va = *a, vb = *b, vc = *c;
    float4 r;
    r.x = va.x + w0 * vb.x + w1 * vc.x;
    r.y = va.y + w0 * vb.y + w1 * vc.y;
    r.z = va.z + w0 * vb.z + w1 * vc.z;
    r.w = va.w + w0 * vb.w + w1 * vc.w;
    *((float4*)(out + (size_t)t * D_MODEL) + tid) = r;
}

// ---------------- launch ------------------------------------------------------------
extern "C" void kernel_launch(void* const* d_in, const int* in_sizes, int n_in,
                              void* d_out, int out_size) {
    const float* x         = (const float*)d_in[0];
    const float* shared_wg = (const float*)d_in[1];
    const float* shared_wu = (const float*)d_in[2];
    const float* shared_wd = (const float*)d_in[3];
    const float* exp_wg    = (const float*)d_in[4];
    const float* exp_wu    = (const float*)d_in[5];
    const float* exp_wd    = (const float*)d_in[6];
    const float* router_w  = (const float*)d_in[7];
    float* out = (float*)d_out;

    __nv_bfloat16 *bg_hi, *bg_lo, *bu_hi, *bu_lo, *bd_hi, *bd_lo;
    cudaGetSymbolAddress((void**)&bg_hi, g_Bg_hi);
    cudaGetSymbolAddress((void**)&bg_lo, g_Bg_lo);
    cudaGetSymbolAddress((void**)&bu_hi, g_Bu_hi);
    cudaGetSymbolAddress((void**)&bu_lo, g_Bu_lo);
    cudaGetSymbolAddress((void**)&bd_hi, g_Bd_hi);
    cudaGetSymbolAddress((void**)&bd_lo, g_Bd_lo);

    cudaFuncSetAttribute(mma_gateup_kernel,
                         cudaFuncAttributeMaxDynamicSharedMemorySize, GU_SMEM);
    cudaFuncSetAttribute(mma_down_kernel,
                         cudaFuncAttributeMaxDynamicSharedMemorySize, DN_SMEM);

    init_kernel<<<(MAXSLOT + 255) / 256, 256>>>();
    router_kernel<<<N_TOK / 4, 128>>>(x, router_w);
    offsets_kernel<<<1, 128>>>(out, out_size);
    scatter_kernel<<<N_TOK / 256, 256>>>();

    conv_x_kernel<<<(N_TOK * D_MODEL) / 256, 256>>>(x);
    conv_w_kernel<<<dim3(D_FFN / 32, D_MODEL / 32, 9), 256>>>(
        shared_wg, exp_wg, bg_hi, bg_lo, D_MODEL, D_FFN);
    conv_w_kernel<<<dim3(D_FFN / 32, D_MODEL / 32, 9), 256>>>(
        shared_wu, exp_wu, bu_hi, bu_lo, D_MODEL, D_FFN);
    conv_w_kernel<<<dim3(D_MODEL / 32, D_FFN / 32, 9), 256>>>(
        shared_wd, exp_wd, bd_hi, bd_lo, D_FFN, D_MODEL);

    mma_gateup_kernel<<<dim3(D_FFN / 64, NT_SH + NT_DN), 256, GU_SMEM>>>();
    mma_down_kernel<<<dim3(D_MODEL / 64, NT_SH + NT_DN), 256, DN_SMEM>>>();
    combine_kernel<<<N_TOK, 256>>>(out);
}

// round 7
// speedup vs baseline: 2.9641x; 1.1546x over previous
#include <cuda_runtime.h>
#include <cuda_bf16.h>
#include <math.h>
#include <stdint.h>

#define D_MODEL 1024
#define D_FFN   2048
#define N_TOK   4096
#define N_EXP   8
#define MAXSLOT 9216
#define NT_SH   (N_TOK / 128)     /* 32 shared row tiles */
#define NT_DN   (MAXSLOT / 128)   /* 72 expert row tiles */

#define TILE_B  10240             /* 128 rows * 80B (padded 64B row) */
#define STG_B   (4 * TILE_B)      /* Ahi, Alo, Bhi, Blo = 40960 */
#define MM_SMEM (2 * STG_B)       /* 81920, 2-stage ring */
#define GU_NSTG 32                /* K=1024 / 32 */
#define DN_NSTG 64                /* K=2048 / 32 */

// ---------------- scratch ----------------------------------------------------
__device__ __nv_bfloat16 g_Xhi[(size_t)N_TOK * D_MODEL];
__device__ __nv_bfloat16 g_Xlo[(size_t)N_TOK * D_MODEL];
// gate+up interleaved: [slab][4096 n][1024 k]; n-chunk c (128 wide) = G cols
// [64c,64c+64) at +0..63, U cols [64c,64c+64) at +64..127
__device__ __nv_bfloat16 g_Bgu_hi[(size_t)9 * 2 * D_FFN * D_MODEL];
__device__ __nv_bfloat16 g_Bgu_lo[(size_t)9 * 2 * D_FFN * D_MODEL];
__device__ __nv_bfloat16 g_Bd_hi[(size_t)9 * D_MODEL * D_FFN];
__device__ __nv_bfloat16 g_Bd_lo[(size_t)9 * D_MODEL * D_FFN];
__device__ __nv_bfloat16 g_Hs_hi[(size_t)N_TOK * D_FFN];
__device__ __nv_bfloat16 g_Hs_lo[(size_t)N_TOK * D_FFN];
__device__ __nv_bfloat16 g_He_hi[(size_t)MAXSLOT * D_FFN];
__device__ __nv_bfloat16 g_He_lo[(size_t)MAXSLOT * D_FFN];
__device__ float g_Os[(size_t)N_TOK * D_MODEL];
__device__ float g_Oe[(size_t)MAXSLOT * D_MODEL];
__device__ int   g_slot_token[MAXSLOT];
__device__ int   g_counts[N_EXP];
__device__ float g_psum[N_EXP];
__device__ int   g_fill[N_EXP];
__device__ int   g_padoff[N_EXP + 1];
__device__ int   g_tile_dn[NT_DN];
__device__ int   g_tok_idx[N_TOK * 2];
__device__ int   g_tok_slot[N_TOK * 2];
__device__ float g_tok_w[N_TOK * 2];

// ---------------- PTX helpers -------------------------------------------------
__device__ __forceinline__ uint32_t s2u(const void* p) {
    return (uint32_t)__cvta_generic_to_shared(p);
}
__device__ __forceinline__ void cpa16(uint32_t dst, const void* src) {
    asm volatile("cp.async.cg.shared.global [%0], [%1], 16;" :: "r"(dst), "l"(src));
}
__device__ __forceinline__ void cp_commit() {
    asm volatile("cp.async.commit_group;");
}
template <int N>
__device__ __forceinline__ void cp_wait() {
    asm volatile("cp.async.wait_group %0;" :: "n"(N));
}
__device__ __forceinline__ void ldm4(uint32_t* r, uint32_t addr) {
    asm volatile("ldmatrix.sync.aligned.m8n8.x4.shared.b16 {%0,%1,%2,%3}, [%4];"
                 : "=r"(r[0]), "=r"(r[1]), "=r"(r[2]), "=r"(r[3]) : "r"(addr));
}
__device__ __forceinline__ void mma_bf16(float* c, const uint32_t* a,
                                         uint32_t b0, uint32_t b1) {
    asm volatile("mma.sync.aligned.m16n8k16.row.col.f32.bf16.bf16.f32 "
                 "{%0,%1,%2,%3}, {%4,%5,%6,%7}, {%8,%9}, {%0,%1,%2,%3};"
                 : "+f"(c[0]), "+f"(c[1]), "+f"(c[2]), "+f"(c[3])
                 : "r"(a[0]), "r"(a[1]), "r"(a[2]), "r"(a[3]), "r"(b0), "r"(b1));
}

// ---------------- routing kernels ---------------------------------------------
__global__ void init_kernel() {
    int i = blockIdx.x * blockDim.x + threadIdx.x;
    if (i < MAXSLOT) g_slot_token[i] = -1;
    if (i < N_EXP) { g_counts[i] = 0; g_psum[i] = 0.f; g_fill[i] = 0; }
}

__global__ void router_kernel(const float* __restrict__ x,
                              const float* __restrict__ rw) {
    int t = blockIdx.x * 4 + (threadIdx.x >> 5);
    int lane = threadIdx.x & 31;
    if (t >= N_TOK) return;
    const float* xr = x + (size_t)t * D_MODEL;
    float acc[N_EXP];
#pragma unroll
    for (int e = 0; e < N_EXP; e++) acc[e] = 0.f;
    for (int k = lane; k < D_MODEL; k += 32) {
        float xv = xr[k];
#pragma unroll
        for (int e = 0; e < N_EXP; e++) acc[e] += xv * rw[k * N_EXP + e];
    }
#pragma unroll
    for (int e = 0; e < N_EXP; e++)
#pragma unroll
        for (int o = 16; o; o >>= 1) acc[e] += __shfl_xor_sync(0xffffffffu, acc[e], o);
    if (lane == 0) {
        int i0 = 0; float v0 = acc[0];
#pragma unroll
        for (int e = 1; e < N_EXP; e++) if (acc[e] > v0) { v0 = acc[e]; i0 = e; }
        int i1 = -1; float v1 = -1e30f;
#pragma unroll
        for (int e = 0; e < N_EXP; e++) {
            if (e == i0) continue;
            if (acc[e] > v1) { v1 = acc[e]; i1 = e; }
        }
        float m2 = fmaxf(v0, v1);
        float e0 = expf(v0 - m2), e1 = expf(v1 - m2);
        float inv = 1.f / (e0 + e1);
        g_tok_idx[t * 2 + 0] = i0;  g_tok_w[t * 2 + 0] = e0 * inv;
        g_tok_idx[t * 2 + 1] = i1;  g_tok_w[t * 2 + 1] = e1 * inv;
        atomicAdd(&g_counts[i0], 1);
        atomicAdd(&g_counts[i1], 1);
        float mm = acc[0];
#pragma unroll
        for (int e = 1; e < N_EXP; e++) mm = fmaxf(mm, acc[e]);
        float s = 0.f, ex[N_EXP];
#pragma unroll
        for (int e = 0; e < N_EXP; e++) { ex[e] = expf(acc[e] - mm); s += ex[e]; }
        float invs = 1.f / s;
#pragma unroll
        for (int e = 0; e < N_EXP; e++) atomicAdd(&g_psum[e], ex[e] * invs);
    }
}

__global__ void offsets_kernel(float* __restrict__ out, int out_size) {
    __shared__ int spad[N_EXP + 1];
    int tid = threadIdx.x;
    if (tid == 0) {
        int off = 0;
        for (int e = 0; e < N_EXP; e++) {
            g_padoff[e] = off;
            off += ((g_counts[e] + 127) / 128) * 128;
        }
        g_padoff[N_EXP] = off;
        for (int e = 0; e <= N_EXP; e++) spad[e] = g_padoff[e];
        double s = 0.0;
        for (int e = 0; e < N_EXP; e++) s += (double)g_counts[e] * (double)g_psum[e];
        float aux = (float)((double)N_EXP * s / ((double)N_TOK * (double)N_TOK));
        if (out_size > N_TOK * D_MODEL) out[(size_t)N_TOK * D_MODEL] = aux;
    }
    __syncthreads();
    for (int j = tid; j < NT_DN; j += blockDim.x) {
        int row = j * 128, te = -1;
#pragma unroll
        for (int e = 0; e < N_EXP; e++)
            if (row >= spad[e] && row < spad[e + 1]) te = e;
        g_tile_dn[j] = te;
    }
}

__global__ void scatter_kernel() {
    int t = blockIdx.x * blockDim.x + threadIdx.x;
    if (t >= N_TOK) return;
#pragma unroll
    for (int k = 0; k < 2; k++) {
        int e = g_tok_idx[t * 2 + k];
        int pos = atomicAdd(&g_fill[e], 1);
        int slot = g_padoff[e] + pos;
        g_slot_token[slot] = t;
        g_tok_slot[t * 2 + k] = slot;
    }
}

// ---------------- conversions --------------------------------------------------
__global__ void conv_x_kernel(const float* __restrict__ x) {
    int i = blockIdx.x * 256 + threadIdx.x;
    float v = x[i];
    __nv_bfloat16 h = __float2bfloat16(v);
    g_Xhi[i] = h;
    g_Xlo[i] = __float2bfloat16(v - __bfloat162float(h));
}

// gate+up -> interleaved [slab][4096 n][1024 k] bf16 hi/lo
__global__ void conv_gu_kernel(const float* __restrict__ srcGs, const float* __restrict__ srcGe,
                               const float* __restrict__ srcUs, const float* __restrict__ srcUe,
                               __nv_bfloat16* __restrict__ hiO, __nv_bfloat16* __restrict__ loO) {
    int slab = blockIdx.z;
    const float* G = (slab == 0) ? srcGs : srcGe + (size_t)(slab - 1) * D_MODEL * D_FFN;
    const float* U = (slab == 0) ? srcUs : srcUe + (size_t)(slab - 1) * D_MODEL * D_FFN;
    size_t ob = (size_t)slab * 2 * D_FFN * D_MODEL;
    __shared__ float tg[32][33], tu[32][33];
    int tx = threadIdx.x & 31, ty = threadIdx.x >> 5;
    int k0 = blockIdx.y * 32, j0 = blockIdx.x * 32;
#pragma unroll
    for (int p = 0; p < 4; p++) {
        size_t so = (size_t)(k0 + p * 8 + ty) * D_FFN + j0 + tx;
        tg[p * 8 + ty][tx] = G[so];
        tu[p * 8 + ty][tx] = U[so];
    }
    __syncthreads();
    int nG0 = ((j0 >> 6) << 7) + (j0 & 63);
#pragma unroll
    for (int p = 0; p < 4; p++) {
        int jj = p * 8 + ty, k = k0 + tx;
        float vg = tg[tx][jj], vu = tu[tx][jj];
        __nv_bfloat16 gh = __float2bfloat16(vg);
        __nv_bfloat16 uh = __float2bfloat16(vu);
        size_t og = ob + (size_t)(nG0 + jj) * D_MODEL + k;
        size_t ou = ob + (size_t)(nG0 + 64 + jj) * D_MODEL + k;
        hiO[og] = gh; loO[og] = __float2bfloat16(vg - __bfloat162float(gh));
        hiO[ou] = uh; loO[ou] = __float2bfloat16(vu - __bfloat162float(uh));
    }
}

// down: transpose [R,C] fp32 -> [slab][C][R] bf16 hi/lo
__global__ void conv_w_kernel(const float* __restrict__ srcS, const float* __restrict__ srcE,
                              __nv_bfloat16* __restrict__ hiO, __nv_bfloat16* __restrict__ loO,
                              int R, int C) {
    int slab = blockIdx.z;
    const float* src = (slab == 0) ? srcS : srcE + (size_t)(slab - 1) * R * C;
    size_t ob = (size_t)slab * R * C;
    __shared__ float t[32][33];
    int tx = threadIdx.x & 31, ty = threadIdx.x >> 5;
    int r0 = blockIdx.y * 32, c0 = blockIdx.x * 32;
#pragma unroll
    for (int p = 0; p < 4; p++)
        t[p * 8 + ty][tx] = src[(size_t)(r0 + p * 8 + ty) * C + c0 + tx];
    __syncthreads();
#pragma unroll
    for (int p = 0; p < 4; p++) {
        int n = c0 + p * 8 + ty, k = r0 + tx;
        float v = t[tx][p * 8 + ty];
        __nv_bfloat16 h = __float2bfloat16(v);
        hiO[ob + (size_t)n * R + k] = h;
        loO[ob + (size_t)n * R + k] = __float2bfloat16(v - __bfloat162float(h));
    }
}

// ---------------- gate+up GEMM: 128M x 128N(=64G+64U), 3-term per K sweep ------
__global__ void __launch_bounds__(256, 2) mma_gateup_kernel() {
    const int by = blockIdx.y;
    const bool sh = (by < NT_SH);
    int te = 0, r0;
    if (sh) r0 = by * 128;
    else {
        int be = by - NT_SH;
        te = g_tile_dn[be];
        if (te < 0) return;
        r0 = be * 128;
    }
    const int slab = sh ? 0 : 1 + te;
    const int n0b = blockIdx.x * 128;        // interleaved B row base
    const int h0 = blockIdx.x * 64;          // H column base
    const int tid = threadIdx.x, lane = tid & 31, wid = tid >> 5;
    const int wm = wid & 3, wn = wid >> 2;

    extern __shared__ __align__(16) char smem[];
    __shared__ int stok[128];
    const uint32_t sbase = s2u(smem);

    if (tid < 128) {
        if (sh) stok[tid] = r0 + tid;
        else { int t = g_slot_token[r0 + tid]; stok[tid] = t < 0 ? 0 : t; }
    }
    __syncthreads();

    const __nv_bfloat16* __restrict__ Bh = g_Bgu_hi + (size_t)slab * 2 * D_FFN * D_MODEL;
    const __nv_bfloat16* __restrict__ Bl = g_Bgu_lo + (size_t)slab * 2 * D_FFN * D_MODEL;

    auto load_stage = [&](int s) {
        const int k0 = s << 5;
        const uint32_t st = sbase + (s & 1) * STG_B;
#pragma unroll
        for (int it = 0; it < 2; it++) {
            int idx = tid + it * 256;
            int row = idx >> 2, ch = idx & 3;
            uint32_t off = row * 80 + ch * 16;
            size_t ao = (size_t)stok[row] * D_MODEL + k0 + ch * 8;
            size_t bo = (size_t)(n0b + row) * D_MODEL + k0 + ch * 8;
            cpa16(st + off,              g_Xhi + ao);
            cpa16(st + TILE_B + off,     g_Xlo + ao);
            cpa16(st + 2 * TILE_B + off, Bh + bo);
            cpa16(st + 3 * TILE_B + off, Bl + bo);
        }
        cp_commit();
    };

    float acc[2][8][4];
#pragma unroll
    for (int i = 0; i < 2; i++)
#pragma unroll
        for (int j = 0; j < 8; j++)
#pragma unroll
            for (int q = 0; q < 4; q++) acc[i][j][q] = 0.f;

    load_stage(0);
    for (int s = 0; s < GU_NSTG; s++) {
        if (s + 1 < GU_NSTG) load_stage(s + 1); else cp_commit();
        cp_wait<1>();
        __syncthreads();
        const uint32_t st = sbase + (s & 1) * STG_B;
        const int lr = lane & 15, lc = (lane >> 4) * 16;
#pragma unroll
        for (int kh = 0; kh < 2; kh++) {
            const int kb = kh * 32 + lc;
            uint32_t ahi[2][4], alo[2][4];
#pragma unroll
            for (int mi = 0; mi < 2; mi++) {
                uint32_t ro = (wm * 32 + mi * 16 + lr) * 80 + kb;
                ldm4(ahi[mi], st + ro);
                ldm4(alo[mi], st + TILE_B + ro);
            }
#pragma unroll
            for (int nj = 0; nj < 4; nj++) {
                uint32_t bh[4], bl[4];
                uint32_t ro = (wn * 64 + nj * 16 + lr) * 80 + kb;
                ldm4(bh, st + 2 * TILE_B + ro);
                ldm4(bl, st + 3 * TILE_B + ro);
#pragma unroll
                for (int mi = 0; mi < 2; mi++) {
                    mma_bf16(acc[mi][nj * 2],     ahi[mi], bh[0], bh[2]);
                    mma_bf16(acc[mi][nj * 2 + 1], ahi[mi], bh[1], bh[3]);
                    mma_bf16(acc[mi][nj * 2],     ahi[mi], bl[0], bl[2]);
                    mma_bf16(acc[mi][nj * 2 + 1], ahi[mi], bl[1], bl[3]);
                    mma_bf16(acc[mi][nj * 2],     alo[mi], bh[0], bh[2]);
                    mma_bf16(acc[mi][nj * 2 + 1], alo[mi], bh[1], bh[3]);
                }
            }
        }
        __syncthreads();
    }

    // SwiGLU epilogue: G warps (wn=0) hand accumulators to U warps (wn=1) via smem
    float* gbuf = (float*)smem;
    if (wn == 0) {
#pragma unroll
        for (int mi = 0; mi < 2; mi++)
#pragma unroll
            for (int ni = 0; ni < 8; ni++)
#pragma unroll
                for (int hh = 0; hh < 2; hh++) {
                    int row = wm * 32 + mi * 16 + (lane >> 2) + hh * 8;
                    int col = ni * 8 + 2 * (lane & 3);
                    float2 v; v.x = acc[mi][ni][hh * 2]; v.y = acc[mi][ni][hh * 2 + 1];
                    *(float2*)(gbuf + row * 66 + col) = v;
                }
    }
    __syncthreads();
    if (wn == 1) {
        __nv_bfloat16* __restrict__ Hhi = sh ? g_Hs_hi : g_He_hi;
        __nv_bfloat16* __restrict__ Hlo = sh ? g_Hs_lo : g_He_lo;
#pragma unroll
        for (int mi = 0; mi < 2; mi++)
#pragma unroll
            for (int ni = 0; ni < 8; ni++)
#pragma unroll
                for (int hh = 0; hh < 2; hh++) {
                    int row = wm * 32 + mi * 16 + (lane >> 2) + hh * 8;
                    int col = ni * 8 + 2 * (lane & 3);
                    float2 g2 = *(const float2*)(gbuf + row * 66 + col);
                    float u0 = acc[mi][ni][hh * 2], u1 = acc[mi][ni][hh * 2 + 1];
                    float h0v = g2.x / (1.f + expf(-g2.x)) * u0;
                    float h1v = g2.y / (1.f + expf(-g2.y)) * u1;
                    __nv_bfloat16 h0h = __float2bfloat16(h0v);
                    __nv_bfloat16 h1h = __float2bfloat16(h1v);
                    __nv_bfloat162 hv; hv.x = h0h; hv.y = h1h;
                    __nv_bfloat162 lv;
                    lv.x = __float2bfloat16(h0v - __bfloat162float(h0h));
                    lv.y = __float2bfloat16(h1v - __bfloat162float(h1h));
                    size_t o = (size_t)(r0 + row) * D_FFN + h0 + col;
                    *(__nv_bfloat162*)(Hhi + o) = hv;
                    *(__nv_bfloat162*)(Hlo + o) = lv;
                }
    }
}

// ---------------- down GEMM: 128M x 128N, 3-term per K sweep --------------------
__global__ void __launch_bounds__(256, 2) mma_down_kernel() {
    const int by = blockIdx.y;
    const bool sh = (by < NT_SH);
    int te = 0, r0;
    if (sh) r0 = by * 128;
    else {
        int be = by - NT_SH;
        te = g_tile_dn[be];
        if (te < 0) return;
        r0 = be * 128;
    }
    const int slab = sh ? 0 : 1 + te;
    const int n0 = blockIdx.x * 128;
    const int tid = threadIdx.x, lane = tid & 31, wid = tid >> 5;
    const int wm = wid & 3, wn = wid >> 2;

    extern __shared__ __align__(16) char smem[];
    const uint32_t sbase = s2u(smem);

    const __nv_bfloat16* __restrict__ Ah = sh ? g_Hs_hi : g_He_hi;
    const __nv_bfloat16* __restrict__ Al = sh ? g_Hs_lo : g_He_lo;
    const __nv_bfloat16* __restrict__ Bh = g_Bd_hi + (size_t)slab * D_MODEL * D_FFN;
    const __nv_bfloat16* __restrict__ Bl = g_Bd_lo + (size_t)slab * D_MODEL * D_FFN;

    auto load_stage = [&](int s) {
        const int k0 = s << 5;
        const uint32_t st = sbase + (s & 1) * STG_B;
#pragma unroll
        for (int it = 0; it < 2; it++) {
            int idx = tid + it * 256;
            int row = idx >> 2, ch = idx & 3;
            uint32_t off = row * 80 + ch * 16;
            size_t ao = (size_t)(r0 + row) * D_FFN + k0 + ch * 8;
            size_t bo = (size_t)(n0 + row) * D_FFN + k0 + ch * 8;
            cpa16(st + off,              Ah + ao);
            cpa16(st + TILE_B + off,     Al + ao);
            cpa16(st + 2 * TILE_B + off, Bh + bo);
            cpa16(st + 3 * TILE_B + off, Bl + bo);
        }
        cp_commit();
    };

    float acc[2][8][4];
#pragma unroll
    for (int i = 0; i < 2; i++)
#pragma unroll
        for (int j = 0; j < 8; j++)
#pragma unroll
            for (int q = 0; q < 4; q++) acc[i][j][q] = 0.f;

    load_stage(0);
    for (int s = 0; s < DN_NSTG; s++) {
        if (s + 1 < DN_NSTG) load_stage(s + 1); else cp_commit();
        cp_wait<1>();
        __syncthreads();
        const uint32_t st = sbase + (s & 1) * STG_B;
        const int lr = lane & 15, lc = (lane >> 4) * 16;
#pragma unroll
        for (int kh = 0; kh < 2; kh++) {
            const int kb = kh * 32 + lc;
            uint32_t ahi[2][4], alo[2][4];
#pragma unroll
            for (int mi = 0; mi < 2; mi++) {
                uint32_t ro = (wm * 32 + mi * 16 + lr) * 80 + kb;
                ldm4(ahi[mi], st + ro);
                ldm4(alo[mi], st + TILE_B + ro);
            }
#pragma unroll
            for (int nj = 0; nj < 4; nj++) {
                uint32_t bh[4], bl[4];
                uint32_t ro = (wn * 64 + nj * 16 + lr) * 80 + kb;
                ldm4(bh, st + 2 * TILE_B + ro);
                ldm4(bl, st + 3 * TILE_B + ro);
#pragma unroll
                for (int mi = 0; mi < 2; mi++) {
                    mma_bf16(acc[mi][nj * 2],     ahi[mi], bh[0], bh[2]);
                    mma_bf16(acc[mi][nj * 2 + 1], ahi[mi], bh[1], bh[3]);
                    mma_bf16(acc[mi][nj * 2],     ahi[mi], bl[0], bl[2]);
                    mma_bf16(acc[mi][nj * 2 + 1], ahi[mi], bl[1], bl[3]);
                    mma_bf16(acc[mi][nj * 2],     alo[mi], bh[0], bh[2]);
                    mma_bf16(acc[mi][nj * 2 + 1], alo[mi], bh[1], bh[3]);
                }
            }
        }
        __syncthreads();
    }

    float* __restrict__ O = sh ? g_Os : g_Oe;
#pragma unroll
    for (int mi = 0; mi < 2; mi++)
#pragma unroll
        for (int ni = 0; ni < 8; ni++)
#pragma unroll
            for (int hh = 0; hh < 2; hh++) {
                int row = wm * 32 + mi * 16 + (lane >> 2) + hh * 8;
                int col = n0 + wn * 64 + ni * 8 + 2 * (lane & 3);
                float2 v; v.x = acc[mi][ni][hh * 2]; v.y = acc[mi][ni][hh * 2 + 1];
                *(float2*)(O + (size_t)(r0 + row) * D_MODEL + col) = v;
            }
}

// ---------------- combine: out = Os + w0*Oe[s0] + w1*Oe[s1] -----------------------
__global__ void combine_kernel(float* __restrict__ out) {
    int t = blockIdx.x;
    int tid = threadIdx.x;
    int s0 = g_tok_slot[t * 2 + 0], s1 = g_tok_slot[t * 2 + 1];
    float w0 = g_tok_w[t * 2 + 0],  w1 = g_tok_w[t * 2 + 1];
    const float4* a = (const float4*)(g_Os + (size_t)t * D_MODEL) + tid;
    const float4* b = (const float4*)(g_Oe + (size_t)s0 * D_MODEL) + tid;
    const float4* c = (const float4*)(g_Oe + (size_t)s1 * D_MODEL) + tid;
    float4 va = *a, vb = *b, vc = *c;
    float4 r;
    r.x = va.x + w0 * vb.x + w1 * vc.x;
    r.y = va.y + w0 * vb.y + w1 * vc.y;
    r.z = va.z + w0 * vb.z + w1 * vc.z;
    r.w = va.w + w0 * vb.w + w1 * vc.w;
    *((float4*)(out + (size_t)t * D_MODEL) + tid) = r;
}

// ---------------- launch ------------------------------------------------------------
extern "C" void kernel_launch(void* const* d_in, const int* in_sizes, int n_in,
                              void* d_out, int out_size) {
    const float* x         = (const float*)d_in[0];
    const float* shared_wg = (const float*)d_in[1];
    const float* shared_wu = (const float*)d_in[2];
    const float* shared_wd = (const float*)d_in[3];
    const float* exp_wg    = (const float*)d_in[4];
    const float* exp_wu    = (const float*)d_in[5];
    const float* exp_wd    = (const float*)d_in[6];
    const float* router_w  = (const float*)d_in[7];
    float* out = (float*)d_out;

    __nv_bfloat16 *bgu_hi, *bgu_lo, *bd_hi, *bd_lo;
    cudaGetSymbolAddress((void**)&bgu_hi, g_Bgu_hi);
    cudaGetSymbolAddress((void**)&bgu_lo, g_Bgu_lo);
    cudaGetSymbolAddress((void**)&bd_hi, g_Bd_hi);
    cudaGetSymbolAddress((void**)&bd_lo, g_Bd_lo);

    cudaFuncSetAttribute(mma_gateup_kernel,
                         cudaFuncAttributeMaxDynamicSharedMemorySize, MM_SMEM);
    cudaFuncSetAttribute(mma_down_kernel,
                         cudaFuncAttributeMaxDynamicSharedMemorySize, MM_SMEM);

    init_kernel<<<(MAXSLOT + 255) / 256, 256>>>();
    router_kernel<<<N_TOK / 4, 128>>>(x, router_w);
    offsets_kernel<<<1, 128>>>(out, out_size);
    scatter_kernel<<<N_TOK / 256, 256>>>();

    conv_x_kernel<<<(N_TOK * D_MODEL) / 256, 256>>>(x);
    conv_gu_kernel<<<dim3(D_FFN / 32, D_MODEL / 32, 9), 256>>>(
        shared_wg, exp_wg, shared_wu, exp_wu, bgu_hi, bgu_lo);
    conv_w_kernel<<<dim3(D_MODEL / 32, D_FFN / 32, 9), 256>>>(
        shared_wd, exp_wd, bd_hi, bd_lo, D_FFN, D_MODEL);

    mma_gateup_kernel<<<dim3(D_FFN / 64, NT_SH + NT_DN), 256, MM_SMEM>>>();
    mma_down_kernel<<<dim3(D_MODEL / 128, NT_SH + NT_DN), 256, MM_SMEM>>>();
    combine_kernel<<<N_TOK, 256>>>(out);
}